// round 14
// baseline (speedup 1.0000x reference)
#include <cuda_runtime.h>
#include <cuda_fp16.h>
#include <math.h>
#include <stdint.h>

#define BATCH 8
#define TT 4096
#define NMELS 26
#define CONV_K 5
#define CH 64
#define WF 32

__device__ uint4 g_xch[262144]; // fp16 conv output (4MB)
__device__ uint4 g_w1h[65536];  // 32 chunks x 32KB fp16 swizzled [n256][k64]
__device__ uint4 g_swh[8192];   //  8 chunks x 16KB [n128][k64]
__device__ uint4 g_w2h[4096];   //  4 chunks x 16KB [n128][k64]

__device__ __forceinline__ uint32_t smem_u32(const void* p) {
    uint32_t a;
    asm("{ .reg .u64 t; cvta.to.shared.u64 t, %1; cvt.u32.u64 %0, t; }" : "=r"(a) : "l"(p));
    return a;
}
__device__ __forceinline__ uint32_t sw128(uint32_t o) { return o ^ ((o >> 3) & 0x70); }
__device__ __forceinline__ void ldsm4(uint32_t (&r)[4], uint32_t a) {
    asm volatile("ldmatrix.sync.aligned.m8n8.x4.shared.b16 {%0,%1,%2,%3}, [%4];"
                 : "=r"(r[0]), "=r"(r[1]), "=r"(r[2]), "=r"(r[3]) : "r"(a));
}
__device__ __forceinline__ void mma16816(float (&d)[4], const uint32_t (&a)[4],
                                         uint32_t b0, uint32_t b1) {
    asm volatile("mma.sync.aligned.m16n8k16.row.col.f32.f16.f16.f32 "
                 "{%0,%1,%2,%3}, {%4,%5,%6,%7}, {%8,%9}, {%0,%1,%2,%3};"
                 : "+f"(d[0]), "+f"(d[1]), "+f"(d[2]), "+f"(d[3])
                 : "r"(a[0]), "r"(a[1]), "r"(a[2]), "r"(a[3]), "r"(b0), "r"(b1));
}
__device__ __forceinline__ void cp16(uint32_t dst, const void* src) {
    asm volatile("cp.async.cg.shared.global [%0], [%1], 16;" :: "r"(dst), "l"(src));
}
#define CP_COMMIT() asm volatile("cp.async.commit_group;" ::: "memory")
#define CP_WAIT(n)  asm volatile("cp.async.wait_group %0;" :: "n"(n) : "memory")

// ---------------------------------------------------------------------------
// fused conv (blocks [0,512), 64 tokens each) + prep tiles (blocks [512,664))
// conv now emits ONLY fp16 g_xch (fp32 copy no longer needed).
// ---------------------------------------------------------------------------
__global__ __launch_bounds__(256, 2) void prep_conv_kernel(
    const float* __restrict__ x, const float* __restrict__ cw,
    const float* __restrict__ cb, const float* __restrict__ w1,
    const float* __restrict__ w2, const float* __restrict__ swp)
{
    __shared__ __align__(16) float sbuf[10152];
    const int tid = threadIdx.x;

    if (blockIdx.x >= 512) {   // ---- prep tile (coalesced transpose) ----
        const int t = blockIdx.x - 512;
        const float* src; unsigned short* dstbase; int N, n0;
        if (t < 128) {
            int f = t >> 2; n0 = (t & 3) * 64;
            src = w1 + (size_t)f * 64 * 256; N = 256;
            dstbase = (unsigned short*)g_w1h + f * 16384;
        } else if (t < 144) {
            int u = t - 128, j = u >> 1; n0 = (u & 1) * 64;
            src = swp + (size_t)j * 64 * 128; N = 128;
            dstbase = (unsigned short*)g_swh + j * 8192;
        } else {
            int u = t - 144, c = u >> 1; n0 = (u & 1) * 64;
            src = w2 + (size_t)c * 64 * 128; N = 128;
            dstbase = (unsigned short*)g_w2h + c * 8192;
        }
        unsigned short* sh = (unsigned short*)sbuf;
        #pragma unroll
        for (int it = 0; it < 16; ++it) {
            int e = it * 256 + tid, kk = e >> 6, nn = e & 63;
            sh[kk * 64 + nn] = __half_as_ushort(__float2half_rn(src[kk * N + n0 + nn]));
        }
        __syncthreads();
        #pragma unroll
        for (int j2 = 0; j2 < 2; ++j2) {
            int G = tid + 256 * j2, n = G >> 3, grp = G & 7, kk0 = grp * 8;
            uint32_t u[4];
            #pragma unroll
            for (int q = 0; q < 4; ++q) {
                uint32_t lo = sh[(kk0 + 2 * q) * 64 + n];
                uint32_t hi = sh[(kk0 + 2 * q + 1) * 64 + n];
                u[q] = lo | (hi << 16);
            }
            uint32_t off = sw128((uint32_t)((n0 + n) * 128 + kk0 * 2));
            *(uint4*)((char*)dstbase + off) = make_uint4(u[0], u[1], u[2], u[3]);
        }
        return;
    }

    // ---- conv: 64 tokens per block ----
    float* xsh = sbuf;             // 68*26 = 1768
    float* wsh = sbuf + 1768;      // 8320
    float* bsh = sbuf + 10088;     // 64
    const int bb = blockIdx.x;
    const int b = bb >> 6, t0 = (bb & 63) << 6;
    for (int idx = tid; idx < 68 * NMELS; idx += 256) {
        int r = idx / NMELS, m = idx - r * NMELS, t = t0 - 4 + r;
        xsh[idx] = (t >= 0) ? x[(b * TT + t) * NMELS + m] : 0.f;
    }
    for (int idx = tid; idx < CONV_K * NMELS * CH; idx += 256) wsh[idx] = cw[idx];
    if (tid < CH) bsh[tid] = cb[tid];
    __syncthreads();
    const int c = tid & 63, tg = tid >> 6;
    unsigned short* xch = (unsigned short*)g_xch;
    #pragma unroll
    for (int g = 0; g < 4; ++g) {
        float acc[4];
        #pragma unroll
        for (int i = 0; i < 4; ++i) acc[i] = bsh[c];
        #pragma unroll
        for (int k = 0; k < CONV_K; ++k)
            #pragma unroll
            for (int m = 0; m < NMELS; ++m) {
                float w = wsh[(k * NMELS + m) * CH + c];
                int base = (tg * 16 + g * 4 + k) * NMELS + m;
                #pragma unroll
                for (int i = 0; i < 4; ++i) acc[i] = fmaf(xsh[base + i * NMELS], w, acc[i]);
            }
        #pragma unroll
        for (int i = 0; i < 4; ++i) {
            size_t idx = (size_t)(b * TT + t0 + tg * 16 + g * 4 + i) * CH + c;
            xch[idx] = __half_as_ushort(__float2half_rn(fmaxf(acc[i], 0.f)));
        }
    }
}

// ---------------------------------------------------------------------------
// main kernel: SE gate fused into the prologue (se_kernel & g_a deleted).
// smem layout identical to Round 11/13 main.
// ---------------------------------------------------------------------------
#define XSH_B 5120
#define AT_B  28160
#define BT_B  93696
#define SMEM_TOT 224768

__device__ __forceinline__ void build_A(uint32_t smb, int f, int slot, int tid,
                                        const uint32_t (&gv)[8])
{
    const int m = tid >> 2, kq = (tid & 3) << 4;
    uint32_t xaddr = smb + XSH_B + (uint32_t)(((m + f) * 72 + kq) * 2);
    uint32_t o = (uint32_t)(m * 128 + kq * 2);
    uint32_t abase = smb + AT_B + (uint32_t)slot * 16384u;
    uint32_t dst0 = abase + sw128(o);
    uint32_t dst1 = abase + sw128(o + 16);
    uint32_t xv[8], h[8];
    asm("ld.shared.v4.b32 {%0,%1,%2,%3}, [%4];"
        : "=r"(xv[0]), "=r"(xv[1]), "=r"(xv[2]), "=r"(xv[3]) : "r"(xaddr));
    asm("ld.shared.v4.b32 {%0,%1,%2,%3}, [%4];"
        : "=r"(xv[4]), "=r"(xv[5]), "=r"(xv[6]), "=r"(xv[7]) : "r"(xaddr + 16));
    #pragma unroll
    for (int i = 0; i < 8; ++i)
        asm("mul.rn.f16x2 %0, %1, %2;" : "=r"(h[i]) : "r"(xv[i]), "r"(gv[i]));
    asm volatile("st.shared.v4.b32 [%0], {%1,%2,%3,%4};"
                 :: "r"(dst0), "r"(h[0]), "r"(h[1]), "r"(h[2]), "r"(h[3]));
    asm volatile("st.shared.v4.b32 [%0], {%1,%2,%3,%4};"
                 :: "r"(dst1), "r"(h[4]), "r"(h[5]), "r"(h[6]), "r"(h[7]));
}

template<int NT>
__device__ __forceinline__ void do_mma(uint32_t abase, uint32_t bbase,
                                       float (&c)[2][NT][4], int wm, int wn, int lane)
{
    uint32_t ra = (uint32_t)((wm * 32 + (lane & 15)) * 128 + ((lane >> 4) << 4));
    uint32_t rb = (uint32_t)((wn * (NT * 8) + (lane & 7) + ((lane >> 4) << 3)) * 128
                             + (((lane >> 3) & 1) << 4));
    #pragma unroll
    for (int ks = 0; ks < 4; ++ks) {
        uint32_t a0[4], a1[4];
        ldsm4(a0, abase + sw128(ra + ks * 32));
        ldsm4(a1, abase + sw128(ra + 2048 + ks * 32));
        #pragma unroll
        for (int nt = 0; nt < NT; nt += 2) {
            uint32_t b4[4];
            ldsm4(b4, bbase + sw128(rb + nt * 1024 + ks * 32));
            mma16816(c[0][nt], a0, b4[0], b4[1]);
            mma16816(c[1][nt], a1, b4[0], b4[1]);
            mma16816(c[0][nt + 1], a0, b4[2], b4[3]);
            mma16816(c[1][nt + 1], a1, b4[2], b4[3]);
        }
    }
}

__device__ __forceinline__ void epi(float (&c)[2][4][4], const float* bias,
                                    const float* wop, float* acc2, int wm, int wn, int lane)
{
    float p[2][2][2];
    #pragma unroll
    for (int mt = 0; mt < 2; ++mt)
        #pragma unroll
        for (int h = 0; h < 2; ++h) { p[mt][h][0] = 0.f; p[mt][h][1] = 0.f; }
    #pragma unroll
    for (int mt = 0; mt < 2; ++mt)
    #pragma unroll
    for (int nt = 0; nt < 4; ++nt) {
        int col = wn * 32 + nt * 8 + 2 * (lane & 3);
        float b0 = bias[col], b1v = bias[col + 1];
        float w00 = wop[2 * col], w01 = wop[2 * col + 1];
        float w10 = wop[2 * col + 2], w11 = wop[2 * col + 3];
        float v;
        v = fmaxf(c[mt][nt][0] + b0, 0.f);  p[mt][0][0] += v * w00; p[mt][0][1] += v * w01;
        v = fmaxf(c[mt][nt][1] + b1v, 0.f); p[mt][0][0] += v * w10; p[mt][0][1] += v * w11;
        v = fmaxf(c[mt][nt][2] + b0, 0.f);  p[mt][1][0] += v * w00; p[mt][1][1] += v * w01;
        v = fmaxf(c[mt][nt][3] + b1v, 0.f); p[mt][1][0] += v * w10; p[mt][1][1] += v * w11;
    }
    #pragma unroll
    for (int mt = 0; mt < 2; ++mt)
        #pragma unroll
        for (int h = 0; h < 2; ++h)
            #pragma unroll
            for (int o = 0; o < 2; ++o) {
                p[mt][h][o] += __shfl_xor_sync(0xffffffffu, p[mt][h][o], 1);
                p[mt][h][o] += __shfl_xor_sync(0xffffffffu, p[mt][h][o], 2);
            }
    if ((lane & 3) == 0)
        #pragma unroll
        for (int mt = 0; mt < 2; ++mt)
            #pragma unroll
            for (int h = 0; h < 2; ++h) {
                int row = wm * 32 + mt * 16 + h * 8 + (lane >> 2);
                atomicAdd(&acc2[row * 2 + 0], p[mt][h][0]);
                atomicAdd(&acc2[row * 2 + 1], p[mt][h][1]);
            }
}

__global__ __launch_bounds__(512, 1) void main_kernel(
    const float* __restrict__ sew1, const float* __restrict__ seb1,
    const float* __restrict__ sew2, const float* __restrict__ seb2,
    const float* __restrict__ b1, const float* __restrict__ b2,
    const float* __restrict__ sb, const float* __restrict__ wo,
    const float* __restrict__ bo, float* __restrict__ out)
{
    extern __shared__ char smc[];
    float* smf = (float*)smc;
    const uint32_t smb = smem_u32(smc);
    const int tid = threadIdx.x, lane = tid & 31, wid = tid >> 5;
    const int wm = wid & 3, wn = wid >> 2;
    const int b = blockIdx.x >> 5, t0 = (blockIdx.x & 31) << 7;
    __half* xsh = (__half*)(smc + XSH_B);

    // B pair0 first (max overlap with rest of prologue)
    {
        uint32_t dst = smb + BT_B + (uint32_t)tid * 16;
        const char* src = (const char*)g_w1h + (size_t)tid * 16;
        #pragma unroll
        for (int r = 0; r < 8; ++r) cp16(dst + r * 8192, src + (size_t)r * 8192);
        CP_COMMIT();
    }
    // XSH from fp16 g_xch via cp.async (159 rows x 8 chunks, stride 144B)
    for (int idx = tid; idx < 159 * 8; idx += 512) {
        int r = idx >> 3, c8 = idx & 7;
        int t = t0 - 31 + r;
        uint32_t d = smb + XSH_B + (uint32_t)(r * 144 + c8 * 16);
        if (t >= 0)
            cp16(d, (const char*)g_xch + (((size_t)b * TT + t) * 64 + c8 * 8) * 2);
        else
            asm volatile("st.shared.v4.b32 [%0], {%1,%1,%1,%1};" :: "r"(d), "r"(0u));
    }
    CP_COMMIT();

    if (tid < 256) smf[tid] = b1[tid];
    if (tid < 128) { smf[256 + tid] = b2[tid]; smf[384 + tid] = sb[tid]; }
    smf[512 + tid] = wo[tid];
    if (tid < 256) smf[1024 + tid] = bo[tid & 1];
    // SE weights -> BT slot 3 (free until h1 loop stages pair 1)
    float* w1s  = (float*)(smc + BT_B + 98304);
    float* w2s  = w1s + 1024;
    float* b1se = w1s + 2048;
    float* b2se = w1s + 2064;
    for (int idx = tid; idx < 1024; idx += 512) { w1s[idx] = sew1[idx]; w2s[idx] = sew2[idx]; }
    if (tid < 16) b1se[tid] = seb1[tid];
    else if (tid >= 32 && tid < 96) b2se[tid - 32] = seb2[tid - 32];

    CP_WAIT(0);
    __syncthreads();   // XSH + B pair0 + SE weights ready

    // ---- fused SE gate: sliding means -> AT slots 0,1 (fp32) ----
    float* sA = (float*)(smc + AT_B);          // [128][64] fp32
    {
        const int c = tid & 63, i0 = (tid >> 6) * 16;
        float s = 0.f;
        #pragma unroll
        for (int r = 0; r < WF; ++r) s += __half2float(xsh[(i0 + r) * 72 + c]);
        sA[i0 * 64 + c] = s * 0.03125f;
        #pragma unroll
        for (int k = 1; k < 16; ++k) {
            s += __half2float(xsh[(i0 + k + 31) * 72 + c])
               - __half2float(xsh[(i0 + k - 1) * 72 + c]);
            sA[(i0 + k) * 64 + c] = s * 0.03125f;
        }
    }
    __syncthreads();
    // ---- SE MLP: a = sigmoid(relu(s@W1+b1)@W2+b2) -> fp16 in AT slot 2 ----
    __half* aH = (__half*)(smc + AT_B + 32768);
    if (tid < 128) {
        const int i = tid;
        float hid[16];
        #pragma unroll
        for (int j = 0; j < 16; ++j) hid[j] = b1se[j];
        for (int c = 0; c < 64; ++c) {
            float sv = sA[i * 64 + c];
            #pragma unroll
            for (int j = 0; j < 16; ++j) hid[j] = fmaf(sv, w1s[c * 16 + j], hid[j]);
        }
        #pragma unroll
        for (int j = 0; j < 16; ++j) hid[j] = fmaxf(hid[j], 0.f);
        for (int c = 0; c < 64; ++c) {
            float v = b2se[c];
            #pragma unroll
            for (int j = 0; j < 16; ++j) v = fmaf(hid[j], w2s[j * 64 + c], v);
            aH[i * 64 + c] = __float2half_rn(1.f / (1.f + expf(-v)));
        }
    }
    __syncthreads();
    // gate row -> registers (fp16x2 pairs, same packing as before)
    uint32_t gv[8];
    {
        const int m = tid >> 2, kq = (tid & 3) << 4;
        const uint32_t* ap = (const uint32_t*)(aH + m * 64 + kq);
        #pragma unroll
        for (int q = 0; q < 8; ++q) gv[q] = ap[q];
    }
    __syncthreads();   // sA/aH reads done; AT slots may be overwritten
    build_A(smb, 0, 0, tid, gv);
    build_A(smb, 1, 1, tid, gv);

    // ----- h1 pass: 16 iterations x 2 frames; cp BEFORE mma -----------------
    float c1[2][8][4];
    #pragma unroll
    for (int i = 0; i < 2; ++i)
        #pragma unroll
        for (int j = 0; j < 8; ++j)
            #pragma unroll
            for (int e = 0; e < 4; ++e) c1[i][j][e] = 0.f;

    for (int f = 0; f < 16; ++f) {
        CP_WAIT(0);
        __syncthreads();
        const int s = f & 1;
        if (f < 15) {   // stage NEXT B pair first -> overlaps the mma below
            const int sn = (f + 1) & 1;
            uint32_t dst = smb + BT_B + (uint32_t)(2 * sn) * 32768u + (uint32_t)tid * 16;
            const char* src = (const char*)g_w1h + (size_t)(2 * f + 2) * 32768
                              + (size_t)tid * 16;
            #pragma unroll
            for (int r = 0; r < 8; ++r) cp16(dst + r * 8192, src + (size_t)r * 8192);
            CP_COMMIT();
        }
        do_mma<8>(smb + AT_B + (uint32_t)(2 * s) * 16384u,
                  smb + BT_B + (uint32_t)(2 * s) * 32768u, c1, wm, wn, lane);
        do_mma<8>(smb + AT_B + (uint32_t)(2 * s + 1) * 16384u,
                  smb + BT_B + (uint32_t)(2 * s + 1) * 32768u, c1, wm, wn, lane);
        if (f < 15) {
            const int sn = (f + 1) & 1;
            build_A(smb, 2 * f + 2, 2 * sn, tid, gv);
            build_A(smb, 2 * f + 3, 2 * sn + 1, tid, gv);
        }
    }
    __syncthreads();   // all h1 reads done

    {   // short prologue: SW chunks 0+1 -> BT slot 2 (cp first), A(24),A(25)
        uint32_t dst = smb + BT_B + 2u * 32768u + (uint32_t)tid * 16;
        const char* src = (const char*)g_swh + (size_t)tid * 16;
        #pragma unroll
        for (int r = 0; r < 4; ++r) cp16(dst + r * 8192, src + (size_t)r * 8192);
        CP_COMMIT();
        build_A(smb, 24, 0, tid, gv);
        build_A(smb, 25, 1, tid, gv);
    }

    // h1 epilogue: relu(+bias) -> fp16 H1 (BT slots 0,1)
    #pragma unroll
    for (int mt = 0; mt < 2; ++mt)
    #pragma unroll
    for (int nt = 0; nt < 8; ++nt) {
        int colw = nt * 8 + 2 * (lane & 3);
        int colg = wn * 64 + colw;
        float b0v = smf[colg], b1v = smf[colg + 1];
        int r = wm * 32 + mt * 16 + (lane >> 2);
        uint32_t base = smb + BT_B + wn * 16384;
        float v0 = fmaxf(c1[mt][nt][0] + b0v, 0.f), v1 = fmaxf(c1[mt][nt][1] + b1v, 0.f);
        float v2 = fmaxf(c1[mt][nt][2] + b0v, 0.f), v3 = fmaxf(c1[mt][nt][3] + b1v, 0.f);
        uint32_t p0, p1;
        asm("cvt.rn.f16x2.f32 %0,%1,%2;" : "=r"(p0) : "f"(v1), "f"(v0));
        asm("cvt.rn.f16x2.f32 %0,%1,%2;" : "=r"(p1) : "f"(v3), "f"(v2));
        asm volatile("st.shared.b32 [%0], %1;" :: "r"(base + sw128(r * 128 + colw * 2)), "r"(p0));
        asm volatile("st.shared.b32 [%0], %1;" :: "r"(base + sw128((r + 8) * 128 + colw * 2)), "r"(p1));
    }

    // ----- short pass: 4 iterations x 2 frames; cp BEFORE mma ---------------
    float cs[2][4][4];
    #pragma unroll
    for (int i = 0; i < 2; ++i)
        #pragma unroll
        for (int j = 0; j < 4; ++j)
            #pragma unroll
            for (int e = 0; e < 4; ++e) cs[i][j][e] = 0.f;
    for (int j = 0; j < 4; ++j) {
        CP_WAIT(0);
        __syncthreads();
        const int s = j & 1;
        if (j < 3) {        // next SW pair
            const int sn = (j + 1) & 1;
            uint32_t dst = smb + BT_B + (uint32_t)(2 + sn) * 32768u + (uint32_t)tid * 16;
            const char* src = (const char*)g_swh + (size_t)(2 * j + 2) * 16384
                              + (size_t)tid * 16;
            #pragma unroll
            for (int r = 0; r < 4; ++r) cp16(dst + r * 8192, src + (size_t)r * 8192);
            CP_COMMIT();
        } else {            // last iter: stage W2 chunks 0,1 -> AT slots 0,1
            uint32_t dst = smb + AT_B + (uint32_t)tid * 16;
            const char* src = (const char*)g_w2h + (size_t)tid * 16;
            #pragma unroll
            for (int r = 0; r < 4; ++r) cp16(dst + r * 8192, src + (size_t)r * 8192);
            CP_COMMIT();
        }
        uint32_t bbase = smb + BT_B + (uint32_t)(2 + s) * 32768u;
        do_mma<4>(smb + AT_B + (uint32_t)(2 * s) * 16384u, bbase, cs, wm, wn, lane);
        do_mma<4>(smb + AT_B + (uint32_t)(2 * s + 1) * 16384u, bbase + 16384u,
                  cs, wm, wn, lane);
        if (j < 3) {
            const int sn = (j + 1) & 1;
            build_A(smb, 26 + 2 * j, 2 * sn, tid, gv);
            build_A(smb, 27 + 2 * j, 2 * sn + 1, tid, gv);
        }
    }
    __syncthreads();   // all short reads of AT slots 2,3 done

    {   // stage W2 chunks 2,3 -> AT slots 2,3
        uint32_t dst = smb + AT_B + 2u * 16384u + (uint32_t)tid * 16;
        const char* src = (const char*)g_w2h + 32768 + (size_t)tid * 16;
        #pragma unroll
        for (int r = 0; r < 4; ++r) cp16(dst + r * 8192, src + (size_t)r * 8192);
        CP_COMMIT();
    }
    epi(cs, smf + 384, smf + 512 + 256, smf + 1024, wm, wn, lane);   // short epi
    CP_WAIT(0);
    __syncthreads();

    // ----- h2 pass: A = H1 (BT 0,1 as 4 chunks), B = W2 (AT), 1 sync ---------
    float ch[2][4][4];
    #pragma unroll
    for (int i = 0; i < 2; ++i)
        #pragma unroll
        for (int j = 0; j < 4; ++j)
            #pragma unroll
            for (int e = 0; e < 4; ++e) ch[i][j][e] = 0.f;
    #pragma unroll
    for (int kc = 0; kc < 4; ++kc)
        do_mma<4>(smb + BT_B + (uint32_t)kc * 16384u,
                  smb + AT_B + (uint32_t)kc * 16384u, ch, wm, wn, lane);
    epi(ch, smf + 256, smf + 512, smf + 1024, wm, wn, lane);

    __syncthreads();
    if (tid < 128) {
        float a0 = smf[1024 + tid * 2], a1 = smf[1024 + tid * 2 + 1];
        float2 o;
        o.x = 1.f / (1.f + expf(-a0));
        o.y = 1.f / (1.f + expf(-a1));
        ((float2*)out)[b * TT + t0 + tid] = o;
    }
}

// ---------------------------------------------------------------------------
extern "C" void kernel_launch(void* const* d_in, const int* in_sizes, int n_in,
                              void* d_out, int out_size)
{
    const float* x      = (const float*)d_in[0];
    const float* conv_w = (const float*)d_in[1];
    const float* conv_b = (const float*)d_in[2];
    const float* se_w1  = (const float*)d_in[3];
    const float* se_b1  = (const float*)d_in[4];
    const float* se_w2  = (const float*)d_in[5];
    const float* se_b2  = (const float*)d_in[6];
    const float* w1     = (const float*)d_in[7];
    const float* b1     = (const float*)d_in[8];
    const float* w2     = (const float*)d_in[9];
    const float* b2     = (const float*)d_in[10];
    const float* sw     = (const float*)d_in[11];
    const float* sb     = (const float*)d_in[12];
    const float* wo     = (const float*)d_in[13];
    const float* bo     = (const float*)d_in[14];
    float* out = (float*)d_out;

    cudaFuncSetAttribute(main_kernel, cudaFuncAttributeMaxDynamicSharedMemorySize, SMEM_TOT);

    prep_conv_kernel<<<664, 256>>>(x, conv_w, conv_b, w1, w2, sw);
    main_kernel<<<BATCH * 32, 512, SMEM_TOT>>>(se_w1, se_b1, se_w2, se_b2,
                                               b1, b2, sb, wo, bo, out);
}

// round 15
// speedup vs baseline: 1.0733x; 1.0733x over previous
#include <cuda_runtime.h>
#include <cuda_fp16.h>
#include <math.h>
#include <stdint.h>

#define BATCH 8
#define TT 4096
#define NMELS 26
#define CONV_K 5
#define CH 64
#define WF 32

__device__ uint4 g_xch[262144]; // fp16 conv output (4MB)
__device__ uint4 g_w1h[65536];  // 32 chunks x 32KB fp16 swizzled [n256][k64]
__device__ uint4 g_swh[8192];   //  8 chunks x 16KB [n128][k64]
__device__ uint4 g_w2h[4096];   //  4 chunks x 16KB [n128][k64]

__device__ __forceinline__ uint32_t smem_u32(const void* p) {
    uint32_t a;
    asm("{ .reg .u64 t; cvta.to.shared.u64 t, %1; cvt.u32.u64 %0, t; }" : "=r"(a) : "l"(p));
    return a;
}
__device__ __forceinline__ uint32_t sw128(uint32_t o) { return o ^ ((o >> 3) & 0x70); }
__device__ __forceinline__ void ldsm4(uint32_t (&r)[4], uint32_t a) {
    asm volatile("ldmatrix.sync.aligned.m8n8.x4.shared.b16 {%0,%1,%2,%3}, [%4];"
                 : "=r"(r[0]), "=r"(r[1]), "=r"(r[2]), "=r"(r[3]) : "r"(a));
}
__device__ __forceinline__ void mma16816(float (&d)[4], const uint32_t (&a)[4],
                                         uint32_t b0, uint32_t b1) {
    asm volatile("mma.sync.aligned.m16n8k16.row.col.f32.f16.f16.f32 "
                 "{%0,%1,%2,%3}, {%4,%5,%6,%7}, {%8,%9}, {%0,%1,%2,%3};"
                 : "+f"(d[0]), "+f"(d[1]), "+f"(d[2]), "+f"(d[3])
                 : "r"(a[0]), "r"(a[1]), "r"(a[2]), "r"(a[3]), "r"(b0), "r"(b1));
}
__device__ __forceinline__ void cp16(uint32_t dst, const void* src) {
    asm volatile("cp.async.cg.shared.global [%0], [%1], 16;" :: "r"(dst), "l"(src));
}
#define CP_COMMIT() asm volatile("cp.async.commit_group;" ::: "memory")
#define CP_WAIT(n)  asm volatile("cp.async.wait_group %0;" :: "n"(n) : "memory")

// ---------------------------------------------------------------------------
// fused conv (blocks [0,512), 64 tokens each) + prep tiles (blocks [512,664))
// ---------------------------------------------------------------------------
__global__ __launch_bounds__(256, 2) void prep_conv_kernel(
    const float* __restrict__ x, const float* __restrict__ cw,
    const float* __restrict__ cb, const float* __restrict__ w1,
    const float* __restrict__ w2, const float* __restrict__ swp)
{
    __shared__ __align__(16) float sbuf[10152];
    const int tid = threadIdx.x;

    if (blockIdx.x >= 512) {   // ---- prep tile (coalesced transpose) ----
        const int t = blockIdx.x - 512;
        const float* src; unsigned short* dstbase; int N, n0;
        if (t < 128) {
            int f = t >> 2; n0 = (t & 3) * 64;
            src = w1 + (size_t)f * 64 * 256; N = 256;
            dstbase = (unsigned short*)g_w1h + f * 16384;
        } else if (t < 144) {
            int u = t - 128, j = u >> 1; n0 = (u & 1) * 64;
            src = swp + (size_t)j * 64 * 128; N = 128;
            dstbase = (unsigned short*)g_swh + j * 8192;
        } else {
            int u = t - 144, c = u >> 1; n0 = (u & 1) * 64;
            src = w2 + (size_t)c * 64 * 128; N = 128;
            dstbase = (unsigned short*)g_w2h + c * 8192;
        }
        unsigned short* sh = (unsigned short*)sbuf;
        #pragma unroll
        for (int it = 0; it < 16; ++it) {
            int e = it * 256 + tid, kk = e >> 6, nn = e & 63;
            sh[kk * 64 + nn] = __half_as_ushort(__float2half_rn(src[kk * N + n0 + nn]));
        }
        __syncthreads();
        #pragma unroll
        for (int j2 = 0; j2 < 2; ++j2) {
            int G = tid + 256 * j2, n = G >> 3, grp = G & 7, kk0 = grp * 8;
            uint32_t u[4];
            #pragma unroll
            for (int q = 0; q < 4; ++q) {
                uint32_t lo = sh[(kk0 + 2 * q) * 64 + n];
                uint32_t hi = sh[(kk0 + 2 * q + 1) * 64 + n];
                u[q] = lo | (hi << 16);
            }
            uint32_t off = sw128((uint32_t)((n0 + n) * 128 + kk0 * 2));
            *(uint4*)((char*)dstbase + off) = make_uint4(u[0], u[1], u[2], u[3]);
        }
        return;
    }

    // ---- conv: 64 tokens per block ----
    float* xsh = sbuf;             // 68*26 = 1768
    float* wsh = sbuf + 1768;      // 8320
    float* bsh = sbuf + 10088;     // 64
    const int bb = blockIdx.x;
    const int b = bb >> 6, t0 = (bb & 63) << 6;
    for (int idx = tid; idx < 68 * NMELS; idx += 256) {
        int r = idx / NMELS, m = idx - r * NMELS, t = t0 - 4 + r;
        xsh[idx] = (t >= 0) ? x[(b * TT + t) * NMELS + m] : 0.f;
    }
    for (int idx = tid; idx < CONV_K * NMELS * CH; idx += 256) wsh[idx] = cw[idx];
    if (tid < CH) bsh[tid] = cb[tid];
    __syncthreads();
    const int c = tid & 63, tg = tid >> 6;
    unsigned short* xch = (unsigned short*)g_xch;
    #pragma unroll
    for (int g = 0; g < 4; ++g) {
        float acc[4];
        #pragma unroll
        for (int i = 0; i < 4; ++i) acc[i] = bsh[c];
        #pragma unroll
        for (int k = 0; k < CONV_K; ++k)
            #pragma unroll
            for (int m = 0; m < NMELS; ++m) {
                float w = wsh[(k * NMELS + m) * CH + c];
                int base = (tg * 16 + g * 4 + k) * NMELS + m;
                #pragma unroll
                for (int i = 0; i < 4; ++i) acc[i] = fmaf(xsh[base + i * NMELS], w, acc[i]);
            }
        #pragma unroll
        for (int i = 0; i < 4; ++i) {
            size_t idx = (size_t)(b * TT + t0 + tg * 16 + g * 4 + i) * CH + c;
            xch[idx] = __half_as_ushort(__float2half_rn(fmaxf(acc[i], 0.f)));
        }
    }
}

// ---------------------------------------------------------------------------
// main kernel: SE gate fused (parallelized across all 512 threads).
// ---------------------------------------------------------------------------
#define XSH_B 5120
#define AT_B  28160
#define BT_B  93696
#define SMEM_TOT 224768

__device__ __forceinline__ void build_A(uint32_t smb, int f, int slot, int tid,
                                        const uint32_t (&gv)[8])
{
    const int m = tid >> 2, kq = (tid & 3) << 4;
    uint32_t xaddr = smb + XSH_B + (uint32_t)(((m + f) * 72 + kq) * 2);
    uint32_t o = (uint32_t)(m * 128 + kq * 2);
    uint32_t abase = smb + AT_B + (uint32_t)slot * 16384u;
    uint32_t dst0 = abase + sw128(o);
    uint32_t dst1 = abase + sw128(o + 16);
    uint32_t xv[8], h[8];
    asm("ld.shared.v4.b32 {%0,%1,%2,%3}, [%4];"
        : "=r"(xv[0]), "=r"(xv[1]), "=r"(xv[2]), "=r"(xv[3]) : "r"(xaddr));
    asm("ld.shared.v4.b32 {%0,%1,%2,%3}, [%4];"
        : "=r"(xv[4]), "=r"(xv[5]), "=r"(xv[6]), "=r"(xv[7]) : "r"(xaddr + 16));
    #pragma unroll
    for (int i = 0; i < 8; ++i)
        asm("mul.rn.f16x2 %0, %1, %2;" : "=r"(h[i]) : "r"(xv[i]), "r"(gv[i]));
    asm volatile("st.shared.v4.b32 [%0], {%1,%2,%3,%4};"
                 :: "r"(dst0), "r"(h[0]), "r"(h[1]), "r"(h[2]), "r"(h[3]));
    asm volatile("st.shared.v4.b32 [%0], {%1,%2,%3,%4};"
                 :: "r"(dst1), "r"(h[4]), "r"(h[5]), "r"(h[6]), "r"(h[7]));
}

template<int NT>
__device__ __forceinline__ void do_mma(uint32_t abase, uint32_t bbase,
                                       float (&c)[2][NT][4], int wm, int wn, int lane)
{
    uint32_t ra = (uint32_t)((wm * 32 + (lane & 15)) * 128 + ((lane >> 4) << 4));
    uint32_t rb = (uint32_t)((wn * (NT * 8) + (lane & 7) + ((lane >> 4) << 3)) * 128
                             + (((lane >> 3) & 1) << 4));
    #pragma unroll
    for (int ks = 0; ks < 4; ++ks) {
        uint32_t a0[4], a1[4];
        ldsm4(a0, abase + sw128(ra + ks * 32));
        ldsm4(a1, abase + sw128(ra + 2048 + ks * 32));
        #pragma unroll
        for (int nt = 0; nt < NT; nt += 2) {
            uint32_t b4[4];
            ldsm4(b4, bbase + sw128(rb + nt * 1024 + ks * 32));
            mma16816(c[0][nt], a0, b4[0], b4[1]);
            mma16816(c[1][nt], a1, b4[0], b4[1]);
            mma16816(c[0][nt + 1], a0, b4[2], b4[3]);
            mma16816(c[1][nt + 1], a1, b4[2], b4[3]);
        }
    }
}

__device__ __forceinline__ void epi(float (&c)[2][4][4], const float* bias,
                                    const float* wop, float* acc2, int wm, int wn, int lane)
{
    float p[2][2][2];
    #pragma unroll
    for (int mt = 0; mt < 2; ++mt)
        #pragma unroll
        for (int h = 0; h < 2; ++h) { p[mt][h][0] = 0.f; p[mt][h][1] = 0.f; }
    #pragma unroll
    for (int mt = 0; mt < 2; ++mt)
    #pragma unroll
    for (int nt = 0; nt < 4; ++nt) {
        int col = wn * 32 + nt * 8 + 2 * (lane & 3);
        float b0 = bias[col], b1v = bias[col + 1];
        float w00 = wop[2 * col], w01 = wop[2 * col + 1];
        float w10 = wop[2 * col + 2], w11 = wop[2 * col + 3];
        float v;
        v = fmaxf(c[mt][nt][0] + b0, 0.f);  p[mt][0][0] += v * w00; p[mt][0][1] += v * w01;
        v = fmaxf(c[mt][nt][1] + b1v, 0.f); p[mt][0][0] += v * w10; p[mt][0][1] += v * w11;
        v = fmaxf(c[mt][nt][2] + b0, 0.f);  p[mt][1][0] += v * w00; p[mt][1][1] += v * w01;
        v = fmaxf(c[mt][nt][3] + b1v, 0.f); p[mt][1][0] += v * w10; p[mt][1][1] += v * w11;
    }
    #pragma unroll
    for (int mt = 0; mt < 2; ++mt)
        #pragma unroll
        for (int h = 0; h < 2; ++h)
            #pragma unroll
            for (int o = 0; o < 2; ++o) {
                p[mt][h][o] += __shfl_xor_sync(0xffffffffu, p[mt][h][o], 1);
                p[mt][h][o] += __shfl_xor_sync(0xffffffffu, p[mt][h][o], 2);
            }
    if ((lane & 3) == 0)
        #pragma unroll
        for (int mt = 0; mt < 2; ++mt)
            #pragma unroll
            for (int h = 0; h < 2; ++h) {
                int row = wm * 32 + mt * 16 + h * 8 + (lane >> 2);
                atomicAdd(&acc2[row * 2 + 0], p[mt][h][0]);
                atomicAdd(&acc2[row * 2 + 1], p[mt][h][1]);
            }
}

__global__ __launch_bounds__(512, 1) void main_kernel(
    const float* __restrict__ sew1, const float* __restrict__ seb1,
    const float* __restrict__ sew2, const float* __restrict__ seb2,
    const float* __restrict__ b1, const float* __restrict__ b2,
    const float* __restrict__ sb, const float* __restrict__ wo,
    const float* __restrict__ bo, float* __restrict__ out)
{
    extern __shared__ char smc[];
    float* smf = (float*)smc;
    const uint32_t smb = smem_u32(smc);
    const int tid = threadIdx.x, lane = tid & 31, wid = tid >> 5;
    const int wm = wid & 3, wn = wid >> 2;
    const int b = blockIdx.x >> 5, t0 = (blockIdx.x & 31) << 7;
    __half* xsh = (__half*)(smc + XSH_B);

    // B pair0 first (max overlap with rest of prologue)
    {
        uint32_t dst = smb + BT_B + (uint32_t)tid * 16;
        const char* src = (const char*)g_w1h + (size_t)tid * 16;
        #pragma unroll
        for (int r = 0; r < 8; ++r) cp16(dst + r * 8192, src + (size_t)r * 8192);
        CP_COMMIT();
    }
    // XSH from fp16 g_xch via cp.async (159 rows x 8 chunks, stride 144B)
    for (int idx = tid; idx < 159 * 8; idx += 512) {
        int r = idx >> 3, c8 = idx & 7;
        int t = t0 - 31 + r;
        uint32_t d = smb + XSH_B + (uint32_t)(r * 144 + c8 * 16);
        if (t >= 0)
            cp16(d, (const char*)g_xch + (((size_t)b * TT + t) * 64 + c8 * 8) * 2);
        else
            asm volatile("st.shared.v4.b32 [%0], {%1,%1,%1,%1};" :: "r"(d), "r"(0u));
    }
    CP_COMMIT();

    if (tid < 256) smf[tid] = b1[tid];
    if (tid < 128) { smf[256 + tid] = b2[tid]; smf[384 + tid] = sb[tid]; }
    smf[512 + tid] = wo[tid];
    if (tid < 256) smf[1024 + tid] = bo[tid & 1];
    // SE weights -> BT slot 3 (free until h1 loop stages pair 1)
    float* w1s  = (float*)(smc + BT_B + 98304);
    float* w2s  = w1s + 1024;
    float* b1se = w1s + 2048;
    float* b2se = w1s + 2064;
    for (int idx = tid; idx < 1024; idx += 512) { w1s[idx] = sew1[idx]; w2s[idx] = sew2[idx]; }
    if (tid < 16) b1se[tid] = seb1[tid];
    else if (tid >= 32 && tid < 96) b2se[tid - 32] = seb2[tid - 32];

    CP_WAIT(0);
    __syncthreads();   // XSH + B pair0 + SE weights ready

    // ---- fused SE: sliding means -> sA [128][stride 65] fp32 ----
    float* sA   = (float*)(smc + AT_B);                 // 33280 B
    __half* aH  = (__half*)(smc + AT_B + 33792);        // 16384 B
    float* hidS = (float*)(smc + AT_B + 50176);         // 128*17*4 = 8704 B
    {
        const int c = tid & 63, i0 = (tid >> 6) * 16;
        float s = 0.f;
        #pragma unroll
        for (int r = 0; r < WF; ++r) s += __half2float(xsh[(i0 + r) * 72 + c]);
        sA[i0 * 65 + c] = s * 0.03125f;
        #pragma unroll
        for (int k = 1; k < 16; ++k) {
            s += __half2float(xsh[(i0 + k + 31) * 72 + c])
               - __half2float(xsh[(i0 + k - 1) * 72 + c]);
            sA[(i0 + k) * 65 + c] = s * 0.03125f;
        }
    }
    __syncthreads();
    // ---- SE MLP stage 1: hid = relu(s@W1+b1), thread = (token, 4 hidden) ----
    {
        const int i = tid >> 2, jg = (tid & 3) << 2;
        float hid[4];
        #pragma unroll
        for (int j = 0; j < 4; ++j) hid[j] = b1se[jg + j];
        for (int c = 0; c < 64; ++c) {
            float sv = sA[i * 65 + c];
            #pragma unroll
            for (int j = 0; j < 4; ++j)
                hid[j] = fmaf(sv, w1s[c * 16 + jg + j], hid[j]);
        }
        #pragma unroll
        for (int j = 0; j < 4; ++j)
            hidS[i * 17 + jg + j] = fmaxf(hid[j], 0.f);
    }
    __syncthreads();
    // ---- SE MLP stage 2: a = sigmoid(hid@W2+b2), thread = (token, 16 cols) --
    {
        const int i = tid >> 2, cg = (tid & 3) << 4;
        float hv[16];
        #pragma unroll
        for (int j = 0; j < 16; ++j) hv[j] = hidS[i * 17 + j];
        #pragma unroll
        for (int c = 0; c < 16; ++c) {
            float v = b2se[cg + c];
            #pragma unroll
            for (int j = 0; j < 16; ++j)
                v = fmaf(hv[j], w2s[j * 64 + cg + c], v);
            aH[i * 64 + cg + c] = __float2half_rn(1.f / (1.f + expf(-v)));
        }
    }
    __syncthreads();
    // gate row -> registers
    uint32_t gv[8];
    {
        const int m = tid >> 2, kq = (tid & 3) << 4;
        const uint32_t* ap = (const uint32_t*)(aH + m * 64 + kq);
        #pragma unroll
        for (int q = 0; q < 8; ++q) gv[q] = ap[q];
    }
    __syncthreads();   // scratch reads done; AT slots may be overwritten
    build_A(smb, 0, 0, tid, gv);
    build_A(smb, 1, 1, tid, gv);

    // ----- h1 pass: 16 iterations x 2 frames; cp BEFORE mma -----------------
    float c1[2][8][4];
    #pragma unroll
    for (int i = 0; i < 2; ++i)
        #pragma unroll
        for (int j = 0; j < 8; ++j)
            #pragma unroll
            for (int e = 0; e < 4; ++e) c1[i][j][e] = 0.f;

    for (int f = 0; f < 16; ++f) {
        CP_WAIT(0);
        __syncthreads();
        const int s = f & 1;
        if (f < 15) {
            const int sn = (f + 1) & 1;
            uint32_t dst = smb + BT_B + (uint32_t)(2 * sn) * 32768u + (uint32_t)tid * 16;
            const char* src = (const char*)g_w1h + (size_t)(2 * f + 2) * 32768
                              + (size_t)tid * 16;
            #pragma unroll
            for (int r = 0; r < 8; ++r) cp16(dst + r * 8192, src + (size_t)r * 8192);
            CP_COMMIT();
        }
        do_mma<8>(smb + AT_B + (uint32_t)(2 * s) * 16384u,
                  smb + BT_B + (uint32_t)(2 * s) * 32768u, c1, wm, wn, lane);
        do_mma<8>(smb + AT_B + (uint32_t)(2 * s + 1) * 16384u,
                  smb + BT_B + (uint32_t)(2 * s + 1) * 32768u, c1, wm, wn, lane);
        if (f < 15) {
            const int sn = (f + 1) & 1;
            build_A(smb, 2 * f + 2, 2 * sn, tid, gv);
            build_A(smb, 2 * f + 3, 2 * sn + 1, tid, gv);
        }
    }
    __syncthreads();   // all h1 reads done

    {   // short prologue: SW chunks 0+1 -> BT slot 2 (cp first), A(24),A(25)
        uint32_t dst = smb + BT_B + 2u * 32768u + (uint32_t)tid * 16;
        const char* src = (const char*)g_swh + (size_t)tid * 16;
        #pragma unroll
        for (int r = 0; r < 4; ++r) cp16(dst + r * 8192, src + (size_t)r * 8192);
        CP_COMMIT();
        build_A(smb, 24, 0, tid, gv);
        build_A(smb, 25, 1, tid, gv);
    }

    // h1 epilogue: relu(+bias) -> fp16 H1 (BT slots 0,1)
    #pragma unroll
    for (int mt = 0; mt < 2; ++mt)
    #pragma unroll
    for (int nt = 0; nt < 8; ++nt) {
        int colw = nt * 8 + 2 * (lane & 3);
        int colg = wn * 64 + colw;
        float b0v = smf[colg], b1v = smf[colg + 1];
        int r = wm * 32 + mt * 16 + (lane >> 2);
        uint32_t base = smb + BT_B + wn * 16384;
        float v0 = fmaxf(c1[mt][nt][0] + b0v, 0.f), v1 = fmaxf(c1[mt][nt][1] + b1v, 0.f);
        float v2 = fmaxf(c1[mt][nt][2] + b0v, 0.f), v3 = fmaxf(c1[mt][nt][3] + b1v, 0.f);
        uint32_t p0, p1;
        asm("cvt.rn.f16x2.f32 %0,%1,%2;" : "=r"(p0) : "f"(v1), "f"(v0));
        asm("cvt.rn.f16x2.f32 %0,%1,%2;" : "=r"(p1) : "f"(v3), "f"(v2));
        asm volatile("st.shared.b32 [%0], %1;" :: "r"(base + sw128(r * 128 + colw * 2)), "r"(p0));
        asm volatile("st.shared.b32 [%0], %1;" :: "r"(base + sw128((r + 8) * 128 + colw * 2)), "r"(p1));
    }

    // ----- short pass: 4 iterations x 2 frames; cp BEFORE mma ---------------
    float cs[2][4][4];
    #pragma unroll
    for (int i = 0; i < 2; ++i)
        #pragma unroll
        for (int j = 0; j < 4; ++j)
            #pragma unroll
            for (int e = 0; e < 4; ++e) cs[i][j][e] = 0.f;
    for (int j = 0; j < 4; ++j) {
        CP_WAIT(0);
        __syncthreads();
        const int s = j & 1;
        if (j < 3) {
            const int sn = (j + 1) & 1;
            uint32_t dst = smb + BT_B + (uint32_t)(2 + sn) * 32768u + (uint32_t)tid * 16;
            const char* src = (const char*)g_swh + (size_t)(2 * j + 2) * 16384
                              + (size_t)tid * 16;
            #pragma unroll
            for (int r = 0; r < 4; ++r) cp16(dst + r * 8192, src + (size_t)r * 8192);
            CP_COMMIT();
        } else {
            uint32_t dst = smb + AT_B + (uint32_t)tid * 16;
            const char* src = (const char*)g_w2h + (size_t)tid * 16;
            #pragma unroll
            for (int r = 0; r < 4; ++r) cp16(dst + r * 8192, src + (size_t)r * 8192);
            CP_COMMIT();
        }
        uint32_t bbase = smb + BT_B + (uint32_t)(2 + s) * 32768u;
        do_mma<4>(smb + AT_B + (uint32_t)(2 * s) * 16384u, bbase, cs, wm, wn, lane);
        do_mma<4>(smb + AT_B + (uint32_t)(2 * s + 1) * 16384u, bbase + 16384u,
                  cs, wm, wn, lane);
        if (j < 3) {
            const int sn = (j + 1) & 1;
            build_A(smb, 26 + 2 * j, 2 * sn, tid, gv);
            build_A(smb, 27 + 2 * j, 2 * sn + 1, tid, gv);
        }
    }
    __syncthreads();   // all short reads of AT slots 2,3 done

    {   // stage W2 chunks 2,3 -> AT slots 2,3
        uint32_t dst = smb + AT_B + 2u * 16384u + (uint32_t)tid * 16;
        const char* src = (const char*)g_w2h + 32768 + (size_t)tid * 16;
        #pragma unroll
        for (int r = 0; r < 4; ++r) cp16(dst + r * 8192, src + (size_t)r * 8192);
        CP_COMMIT();
    }
    epi(cs, smf + 384, smf + 512 + 256, smf + 1024, wm, wn, lane);   // short epi
    CP_WAIT(0);
    __syncthreads();

    // ----- h2 pass: A = H1 (BT 0,1 as 4 chunks), B = W2 (AT), 1 sync ---------
    float ch[2][4][4];
    #pragma unroll
    for (int i = 0; i < 2; ++i)
        #pragma unroll
        for (int j = 0; j < 4; ++j)
            #pragma unroll
            for (int e = 0; e < 4; ++e) ch[i][j][e] = 0.f;
    #pragma unroll
    for (int kc = 0; kc < 4; ++kc)
        do_mma<4>(smb + BT_B + (uint32_t)kc * 16384u,
                  smb + AT_B + (uint32_t)kc * 16384u, ch, wm, wn, lane);
    epi(ch, smf + 256, smf + 512, smf + 1024, wm, wn, lane);

    __syncthreads();
    if (tid < 128) {
        float a0 = smf[1024 + tid * 2], a1 = smf[1024 + tid * 2 + 1];
        float2 o;
        o.x = 1.f / (1.f + expf(-a0));
        o.y = 1.f / (1.f + expf(-a1));
        ((float2*)out)[b * TT + t0 + tid] = o;
    }
}

// ---------------------------------------------------------------------------
extern "C" void kernel_launch(void* const* d_in, const int* in_sizes, int n_in,
                              void* d_out, int out_size)
{
    const float* x      = (const float*)d_in[0];
    const float* conv_w = (const float*)d_in[1];
    const float* conv_b = (const float*)d_in[2];
    const float* se_w1  = (const float*)d_in[3];
    const float* se_b1  = (const float*)d_in[4];
    const float* se_w2  = (const float*)d_in[5];
    const float* se_b2  = (const float*)d_in[6];
    const float* w1     = (const float*)d_in[7];
    const float* b1     = (const float*)d_in[8];
    const float* w2     = (const float*)d_in[9];
    const float* b2     = (const float*)d_in[10];
    const float* sw     = (const float*)d_in[11];
    const float* sb     = (const float*)d_in[12];
    const float* wo     = (const float*)d_in[13];
    const float* bo     = (const float*)d_in[14];
    float* out = (float*)d_out;

    cudaFuncSetAttribute(main_kernel, cudaFuncAttributeMaxDynamicSharedMemorySize, SMEM_TOT);

    prep_conv_kernel<<<664, 256>>>(x, conv_w, conv_b, w1, w2, sw);
    main_kernel<<<BATCH * 32, 512, SMEM_TOT>>>(se_w1, se_b1, se_w2, se_b2,
                                               b1, b2, sb, wo, bo, out);
}

// round 16
// speedup vs baseline: 1.0752x; 1.0018x over previous
#include <cuda_runtime.h>
#include <cuda_fp16.h>
#include <math.h>
#include <stdint.h>

#define BATCH 8
#define TT 4096
#define NMELS 26
#define CONV_K 5
#define CH 64
#define WF 32

__device__ uint4 g_w1h[65536];  // 32 chunks x 32KB fp16 swizzled [n256][k64]
__device__ uint4 g_swh[8192];   //  8 chunks x 16KB [n128][k64]
__device__ uint4 g_w2h[4096];   //  4 chunks x 16KB [n128][k64]

__device__ __forceinline__ uint32_t smem_u32(const void* p) {
    uint32_t a;
    asm("{ .reg .u64 t; cvta.to.shared.u64 t, %1; cvt.u32.u64 %0, t; }" : "=r"(a) : "l"(p));
    return a;
}
__device__ __forceinline__ uint32_t sw128(uint32_t o) { return o ^ ((o >> 3) & 0x70); }
__device__ __forceinline__ void ldsm4(uint32_t (&r)[4], uint32_t a) {
    asm volatile("ldmatrix.sync.aligned.m8n8.x4.shared.b16 {%0,%1,%2,%3}, [%4];"
                 : "=r"(r[0]), "=r"(r[1]), "=r"(r[2]), "=r"(r[3]) : "r"(a));
}
__device__ __forceinline__ void mma16816(float (&d)[4], const uint32_t (&a)[4],
                                         uint32_t b0, uint32_t b1) {
    asm volatile("mma.sync.aligned.m16n8k16.row.col.f32.f16.f16.f32 "
                 "{%0,%1,%2,%3}, {%4,%5,%6,%7}, {%8,%9}, {%0,%1,%2,%3};"
                 : "+f"(d[0]), "+f"(d[1]), "+f"(d[2]), "+f"(d[3])
                 : "r"(a[0]), "r"(a[1]), "r"(a[2]), "r"(a[3]), "r"(b0), "r"(b1));
}
__device__ __forceinline__ void cp16(uint32_t dst, const void* src) {
    asm volatile("cp.async.cg.shared.global [%0], [%1], 16;" :: "r"(dst), "l"(src));
}
#define CP_COMMIT() asm volatile("cp.async.commit_group;" ::: "memory")
#define CP_WAIT(n)  asm volatile("cp.async.wait_group %0;" :: "n"(n) : "memory")

// ---------------------------------------------------------------------------
// prep kernel: 152 blocks, coalesced 64k x 64n weight transpose -> fp16 images
// ---------------------------------------------------------------------------
__global__ __launch_bounds__(256, 4) void prep_kernel(
    const float* __restrict__ w1, const float* __restrict__ w2,
    const float* __restrict__ swp)
{
    __shared__ __align__(16) unsigned short sh[4096];
    const int tid = threadIdx.x;
    const int t = blockIdx.x;
    const float* src; unsigned short* dstbase; int N, n0;
    if (t < 128) {
        int f = t >> 2; n0 = (t & 3) * 64;
        src = w1 + (size_t)f * 64 * 256; N = 256;
        dstbase = (unsigned short*)g_w1h + f * 16384;
    } else if (t < 144) {
        int u = t - 128, j = u >> 1; n0 = (u & 1) * 64;
        src = swp + (size_t)j * 64 * 128; N = 128;
        dstbase = (unsigned short*)g_swh + j * 8192;
    } else {
        int u = t - 144, c = u >> 1; n0 = (u & 1) * 64;
        src = w2 + (size_t)c * 64 * 128; N = 128;
        dstbase = (unsigned short*)g_w2h + c * 8192;
    }
    #pragma unroll
    for (int it = 0; it < 16; ++it) {
        int e = it * 256 + tid, kk = e >> 6, nn = e & 63;
        sh[kk * 64 + nn] = __half_as_ushort(__float2half_rn(src[kk * N + n0 + nn]));
    }
    __syncthreads();
    #pragma unroll
    for (int j2 = 0; j2 < 2; ++j2) {
        int G = tid + 256 * j2, n = G >> 3, grp = G & 7, kk0 = grp * 8;
        uint32_t u[4];
        #pragma unroll
        for (int q = 0; q < 4; ++q) {
            uint32_t lo = sh[(kk0 + 2 * q) * 64 + n];
            uint32_t hi = sh[(kk0 + 2 * q + 1) * 64 + n];
            u[q] = lo | (hi << 16);
        }
        uint32_t off = sw128((uint32_t)((n0 + n) * 128 + kk0 * 2));
        *(uint4*)((char*)dstbase + off) = make_uint4(u[0], u[1], u[2], u[3]);
    }
}

// ---------------------------------------------------------------------------
// main kernel: conv + SE + all GEMMs fused. 256 CTAs x 128 tokens, 512 thr.
// smem: misc@0(5120) | XSH@5120 (160x72 halves) | AT@28160 (4x16KB) |
//       BT@93696 (4x32KB). During prologue BT slots 2,3 hold:
//         cvw@+65536 (33280B) | xs@+98816 (164x26 f32 =17056B) |
//         SEw@+115872 (8512B) | cb@+124384 (256B)
// ---------------------------------------------------------------------------
#define XSH_B 5120
#define AT_B  28160
#define BT_B  93696
#define CVW_B (BT_B + 65536)
#define CVX_B (BT_B + 98816)
#define SEW_B (BT_B + 115872)
#define CBS_B (BT_B + 124384)
#define SMEM_TOT 224768

__device__ __forceinline__ void build_A(uint32_t smb, int f, int slot, int tid,
                                        const uint32_t (&gv)[8])
{
    const int m = tid >> 2, kq = (tid & 3) << 4;
    uint32_t xaddr = smb + XSH_B + (uint32_t)(((m + f) * 72 + kq) * 2);
    uint32_t o = (uint32_t)(m * 128 + kq * 2);
    uint32_t abase = smb + AT_B + (uint32_t)slot * 16384u;
    uint32_t dst0 = abase + sw128(o);
    uint32_t dst1 = abase + sw128(o + 16);
    uint32_t xv[8], h[8];
    asm("ld.shared.v4.b32 {%0,%1,%2,%3}, [%4];"
        : "=r"(xv[0]), "=r"(xv[1]), "=r"(xv[2]), "=r"(xv[3]) : "r"(xaddr));
    asm("ld.shared.v4.b32 {%0,%1,%2,%3}, [%4];"
        : "=r"(xv[4]), "=r"(xv[5]), "=r"(xv[6]), "=r"(xv[7]) : "r"(xaddr + 16));
    #pragma unroll
    for (int i = 0; i < 8; ++i)
        asm("mul.rn.f16x2 %0, %1, %2;" : "=r"(h[i]) : "r"(xv[i]), "r"(gv[i]));
    asm volatile("st.shared.v4.b32 [%0], {%1,%2,%3,%4};"
                 :: "r"(dst0), "r"(h[0]), "r"(h[1]), "r"(h[2]), "r"(h[3]));
    asm volatile("st.shared.v4.b32 [%0], {%1,%2,%3,%4};"
                 :: "r"(dst1), "r"(h[4]), "r"(h[5]), "r"(h[6]), "r"(h[7]));
}

template<int NT>
__device__ __forceinline__ void do_mma(uint32_t abase, uint32_t bbase,
                                       float (&c)[2][NT][4], int wm, int wn, int lane)
{
    uint32_t ra = (uint32_t)((wm * 32 + (lane & 15)) * 128 + ((lane >> 4) << 4));
    uint32_t rb = (uint32_t)((wn * (NT * 8) + (lane & 7) + ((lane >> 4) << 3)) * 128
                             + (((lane >> 3) & 1) << 4));
    #pragma unroll
    for (int ks = 0; ks < 4; ++ks) {
        uint32_t a0[4], a1[4];
        ldsm4(a0, abase + sw128(ra + ks * 32));
        ldsm4(a1, abase + sw128(ra + 2048 + ks * 32));
        #pragma unroll
        for (int nt = 0; nt < NT; nt += 2) {
            uint32_t b4[4];
            ldsm4(b4, bbase + sw128(rb + nt * 1024 + ks * 32));
            mma16816(c[0][nt], a0, b4[0], b4[1]);
            mma16816(c[1][nt], a1, b4[0], b4[1]);
            mma16816(c[0][nt + 1], a0, b4[2], b4[3]);
            mma16816(c[1][nt + 1], a1, b4[2], b4[3]);
        }
    }
}

__device__ __forceinline__ void epi(float (&c)[2][4][4], const float* bias,
                                    const float* wop, float* acc2, int wm, int wn, int lane)
{
    float p[2][2][2];
    #pragma unroll
    for (int mt = 0; mt < 2; ++mt)
        #pragma unroll
        for (int h = 0; h < 2; ++h) { p[mt][h][0] = 0.f; p[mt][h][1] = 0.f; }
    #pragma unroll
    for (int mt = 0; mt < 2; ++mt)
    #pragma unroll
    for (int nt = 0; nt < 4; ++nt) {
        int col = wn * 32 + nt * 8 + 2 * (lane & 3);
        float b0 = bias[col], b1v = bias[col + 1];
        float w00 = wop[2 * col], w01 = wop[2 * col + 1];
        float w10 = wop[2 * col + 2], w11 = wop[2 * col + 3];
        float v;
        v = fmaxf(c[mt][nt][0] + b0, 0.f);  p[mt][0][0] += v * w00; p[mt][0][1] += v * w01;
        v = fmaxf(c[mt][nt][1] + b1v, 0.f); p[mt][0][0] += v * w10; p[mt][0][1] += v * w11;
        v = fmaxf(c[mt][nt][2] + b0, 0.f);  p[mt][1][0] += v * w00; p[mt][1][1] += v * w01;
        v = fmaxf(c[mt][nt][3] + b1v, 0.f); p[mt][1][0] += v * w10; p[mt][1][1] += v * w11;
    }
    #pragma unroll
    for (int mt = 0; mt < 2; ++mt)
        #pragma unroll
        for (int h = 0; h < 2; ++h)
            #pragma unroll
            for (int o = 0; o < 2; ++o) {
                p[mt][h][o] += __shfl_xor_sync(0xffffffffu, p[mt][h][o], 1);
                p[mt][h][o] += __shfl_xor_sync(0xffffffffu, p[mt][h][o], 2);
            }
    if ((lane & 3) == 0)
        #pragma unroll
        for (int mt = 0; mt < 2; ++mt)
            #pragma unroll
            for (int h = 0; h < 2; ++h) {
                int row = wm * 32 + mt * 16 + h * 8 + (lane >> 2);
                atomicAdd(&acc2[row * 2 + 0], p[mt][h][0]);
                atomicAdd(&acc2[row * 2 + 1], p[mt][h][1]);
            }
}

__global__ __launch_bounds__(512, 1) void main_kernel(
    const float* __restrict__ x, const float* __restrict__ cw,
    const float* __restrict__ cb,
    const float* __restrict__ sew1, const float* __restrict__ seb1,
    const float* __restrict__ sew2, const float* __restrict__ seb2,
    const float* __restrict__ b1, const float* __restrict__ b2,
    const float* __restrict__ sb, const float* __restrict__ wo,
    const float* __restrict__ bo, float* __restrict__ out)
{
    extern __shared__ char smc[];
    float* smf = (float*)smc;
    const uint32_t smb = smem_u32(smc);
    const int tid = threadIdx.x, lane = tid & 31, wid = tid >> 5;
    const int wm = wid & 3, wn = wid >> 2;
    const int b = blockIdx.x >> 5, t0 = (blockIdx.x & 31) << 7;
    __half* xsh = (__half*)(smc + XSH_B);

    // B pair0 + conv weights via cp.async
    {
        uint32_t dst = smb + BT_B + (uint32_t)tid * 16;
        const char* src = (const char*)g_w1h + (size_t)tid * 16;
        #pragma unroll
        for (int r = 0; r < 8; ++r) cp16(dst + r * 8192, src + (size_t)r * 8192);
        for (int i = tid; i < 2080; i += 512)
            cp16(smb + CVW_B + (uint32_t)i * 16, (const char*)cw + (size_t)i * 16);
        CP_COMMIT();
    }
    // x slab (tokens t0-35..t0+127, zeros for t<0) -> fp32 smem
    {
        float* xs = (float*)(smc + CVX_B);
        for (int idx = tid; idx < 164 * 26; idx += 512) {
            int rr = idx / 26, mm = idx - rr * 26;
            int t = t0 - 35 + rr;
            float v = 0.f;
            if (t >= 0 && rr < 163) v = x[((size_t)b * TT + t) * 26 + mm];
            xs[idx] = v;
        }
    }
    if (tid < 256) smf[tid] = b1[tid];
    if (tid < 128) { smf[256 + tid] = b2[tid]; smf[384 + tid] = sb[tid]; }
    smf[512 + tid] = wo[tid];
    if (tid < 256) smf[1024 + tid] = bo[tid & 1];
    // SE weights + conv bias -> BT slot3 tail
    float* w1s  = (float*)(smc + SEW_B);
    float* w2s  = w1s + 1024;
    float* b1se = w1s + 2048;
    float* b2se = w1s + 2064;
    float* cbs  = (float*)(smc + CBS_B);
    for (int idx = tid; idx < 1024; idx += 512) { w1s[idx] = sew1[idx]; w2s[idx] = sew2[idx]; }
    if (tid < 16) b1se[tid] = seb1[tid];
    else if (tid >= 32 && tid < 96) b2se[tid - 32] = seb2[tid - 32];
    else if (tid >= 128 && tid < 192) cbs[tid - 128] = cb[tid - 128];

    CP_WAIT(0);
    __syncthreads();   // cvw + xs + B pair0 + SE weights ready

    // ---- fused conv: rows 0..158 (tokens t0-31..t0+127) -> XSH fp16 --------
    {
        const int c = tid & 63, rg = tid >> 6;
        const float* xs = (const float*)(smc + CVX_B);
        const float* ws = (const float*)(smc + CVW_B);
        const float cbv = cbs[c];
        for (int sg = 0; sg < 5; ++sg) {
            const int r0 = rg * 20 + sg * 4;
            float acc[4] = {cbv, cbv, cbv, cbv};
            for (int m = 0; m < NMELS; ++m) {
                float xr[8];
                #pragma unroll
                for (int i = 0; i < 8; ++i) xr[i] = xs[(r0 + i) * 26 + m];
                #pragma unroll
                for (int k = 0; k < CONV_K; ++k) {
                    float w = ws[(k * NMELS + m) * 64 + c];
                    #pragma unroll
                    for (int i = 0; i < 4; ++i)
                        acc[i] = fmaf(xr[k + i], w, acc[i]);
                }
            }
            #pragma unroll
            for (int i = 0; i < 4; ++i) {
                int r = r0 + i;
                if (r < 159) {
                    float v = (t0 - 31 + r < 0) ? 0.f : fmaxf(acc[i], 0.f);
                    xsh[r * 72 + c] = __float2half_rn(v);
                }
            }
        }
    }
    __syncthreads();

    // ---- fused SE: sliding means -> sA [128][65] fp32 ----
    float* sA   = (float*)(smc + AT_B);
    __half* aH  = (__half*)(smc + AT_B + 33792);
    float* hidS = (float*)(smc + AT_B + 50176);
    {
        const int c = tid & 63, i0 = (tid >> 6) * 16;
        float s = 0.f;
        #pragma unroll
        for (int r = 0; r < WF; ++r) s += __half2float(xsh[(i0 + r) * 72 + c]);
        sA[i0 * 65 + c] = s * 0.03125f;
        #pragma unroll
        for (int k = 1; k < 16; ++k) {
            s += __half2float(xsh[(i0 + k + 31) * 72 + c])
               - __half2float(xsh[(i0 + k - 1) * 72 + c]);
            sA[(i0 + k) * 65 + c] = s * 0.03125f;
        }
    }
    __syncthreads();
    {   // MLP stage 1: thread = (token, 4 hidden)
        const int i = tid >> 2, jg = (tid & 3) << 2;
        float hid[4];
        #pragma unroll
        for (int j = 0; j < 4; ++j) hid[j] = b1se[jg + j];
        for (int c = 0; c < 64; ++c) {
            float sv = sA[i * 65 + c];
            #pragma unroll
            for (int j = 0; j < 4; ++j)
                hid[j] = fmaf(sv, w1s[c * 16 + jg + j], hid[j]);
        }
        #pragma unroll
        for (int j = 0; j < 4; ++j)
            hidS[i * 17 + jg + j] = fmaxf(hid[j], 0.f);
    }
    __syncthreads();
    {   // MLP stage 2: thread = (token, 16 cols)
        const int i = tid >> 2, cg = (tid & 3) << 4;
        float hv[16];
        #pragma unroll
        for (int j = 0; j < 16; ++j) hv[j] = hidS[i * 17 + j];
        #pragma unroll
        for (int c = 0; c < 16; ++c) {
            float v = b2se[cg + c];
            #pragma unroll
            for (int j = 0; j < 16; ++j)
                v = fmaf(hv[j], w2s[j * 64 + cg + c], v);
            aH[i * 64 + cg + c] = __float2half_rn(1.f / (1.f + expf(-v)));
        }
    }
    __syncthreads();
    uint32_t gv[8];
    {
        const int m = tid >> 2, kq = (tid & 3) << 4;
        const uint32_t* ap = (const uint32_t*)(aH + m * 64 + kq);
        #pragma unroll
        for (int q = 0; q < 8; ++q) gv[q] = ap[q];
    }
    __syncthreads();
    build_A(smb, 0, 0, tid, gv);
    build_A(smb, 1, 1, tid, gv);

    // ----- h1 pass: 16 iterations x 2 frames; cp BEFORE mma -----------------
    float c1[2][8][4];
    #pragma unroll
    for (int i = 0; i < 2; ++i)
        #pragma unroll
        for (int j = 0; j < 8; ++j)
            #pragma unroll
            for (int e = 0; e < 4; ++e) c1[i][j][e] = 0.f;

    for (int f = 0; f < 16; ++f) {
        CP_WAIT(0);
        __syncthreads();
        const int s = f & 1;
        if (f < 15) {
            const int sn = (f + 1) & 1;
            uint32_t dst = smb + BT_B + (uint32_t)(2 * sn) * 32768u + (uint32_t)tid * 16;
            const char* src = (const char*)g_w1h + (size_t)(2 * f + 2) * 32768
                              + (size_t)tid * 16;
            #pragma unroll
            for (int r = 0; r < 8; ++r) cp16(dst + r * 8192, src + (size_t)r * 8192);
            CP_COMMIT();
        }
        do_mma<8>(smb + AT_B + (uint32_t)(2 * s) * 16384u,
                  smb + BT_B + (uint32_t)(2 * s) * 32768u, c1, wm, wn, lane);
        do_mma<8>(smb + AT_B + (uint32_t)(2 * s + 1) * 16384u,
                  smb + BT_B + (uint32_t)(2 * s + 1) * 32768u, c1, wm, wn, lane);
        if (f < 15) {
            const int sn = (f + 1) & 1;
            build_A(smb, 2 * f + 2, 2 * sn, tid, gv);
            build_A(smb, 2 * f + 3, 2 * sn + 1, tid, gv);
        }
    }
    __syncthreads();

    {   // short prologue
        uint32_t dst = smb + BT_B + 2u * 32768u + (uint32_t)tid * 16;
        const char* src = (const char*)g_swh + (size_t)tid * 16;
        #pragma unroll
        for (int r = 0; r < 4; ++r) cp16(dst + r * 8192, src + (size_t)r * 8192);
        CP_COMMIT();
        build_A(smb, 24, 0, tid, gv);
        build_A(smb, 25, 1, tid, gv);
    }

    // h1 epilogue: relu(+bias) -> fp16 H1 (BT slots 0,1)
    #pragma unroll
    for (int mt = 0; mt < 2; ++mt)
    #pragma unroll
    for (int nt = 0; nt < 8; ++nt) {
        int colw = nt * 8 + 2 * (lane & 3);
        int colg = wn * 64 + colw;
        float b0v = smf[colg], b1v = smf[colg + 1];
        int r = wm * 32 + mt * 16 + (lane >> 2);
        uint32_t base = smb + BT_B + wn * 16384;
        float v0 = fmaxf(c1[mt][nt][0] + b0v, 0.f), v1 = fmaxf(c1[mt][nt][1] + b1v, 0.f);
        float v2 = fmaxf(c1[mt][nt][2] + b0v, 0.f), v3 = fmaxf(c1[mt][nt][3] + b1v, 0.f);
        uint32_t p0, p1;
        asm("cvt.rn.f16x2.f32 %0,%1,%2;" : "=r"(p0) : "f"(v1), "f"(v0));
        asm("cvt.rn.f16x2.f32 %0,%1,%2;" : "=r"(p1) : "f"(v3), "f"(v2));
        asm volatile("st.shared.b32 [%0], %1;" :: "r"(base + sw128(r * 128 + colw * 2)), "r"(p0));
        asm volatile("st.shared.b32 [%0], %1;" :: "r"(base + sw128((r + 8) * 128 + colw * 2)), "r"(p1));
    }

    // ----- short pass: 4 iterations x 2 frames -------------------------------
    float cs[2][4][4];
    #pragma unroll
    for (int i = 0; i < 2; ++i)
        #pragma unroll
        for (int j = 0; j < 4; ++j)
            #pragma unroll
            for (int e = 0; e < 4; ++e) cs[i][j][e] = 0.f;
    for (int j = 0; j < 4; ++j) {
        CP_WAIT(0);
        __syncthreads();
        const int s = j & 1;
        if (j < 3) {
            const int sn = (j + 1) & 1;
            uint32_t dst = smb + BT_B + (uint32_t)(2 + sn) * 32768u + (uint32_t)tid * 16;
            const char* src = (const char*)g_swh + (size_t)(2 * j + 2) * 16384
                              + (size_t)tid * 16;
            #pragma unroll
            for (int r = 0; r < 4; ++r) cp16(dst + r * 8192, src + (size_t)r * 8192);
            CP_COMMIT();
        } else {
            uint32_t dst = smb + AT_B + (uint32_t)tid * 16;
            const char* src = (const char*)g_w2h + (size_t)tid * 16;
            #pragma unroll
            for (int r = 0; r < 4; ++r) cp16(dst + r * 8192, src + (size_t)r * 8192);
            CP_COMMIT();
        }
        uint32_t bbase = smb + BT_B + (uint32_t)(2 + s) * 32768u;
        do_mma<4>(smb + AT_B + (uint32_t)(2 * s) * 16384u, bbase, cs, wm, wn, lane);
        do_mma<4>(smb + AT_B + (uint32_t)(2 * s + 1) * 16384u, bbase + 16384u,
                  cs, wm, wn, lane);
        if (j < 3) {
            const int sn = (j + 1) & 1;
            build_A(smb, 26 + 2 * j, 2 * sn, tid, gv);
            build_A(smb, 27 + 2 * j, 2 * sn + 1, tid, gv);
        }
    }
    __syncthreads();

    {   // stage W2 chunks 2,3 -> AT slots 2,3
        uint32_t dst = smb + AT_B + 2u * 16384u + (uint32_t)tid * 16;
        const char* src = (const char*)g_w2h + 32768 + (size_t)tid * 16;
        #pragma unroll
        for (int r = 0; r < 4; ++r) cp16(dst + r * 8192, src + (size_t)r * 8192);
        CP_COMMIT();
    }
    epi(cs, smf + 384, smf + 512 + 256, smf + 1024, wm, wn, lane);
    CP_WAIT(0);
    __syncthreads();

    // ----- h2 pass ------------------------------------------------------------
    float ch[2][4][4];
    #pragma unroll
    for (int i = 0; i < 2; ++i)
        #pragma unroll
        for (int j = 0; j < 4; ++j)
            #pragma unroll
            for (int e = 0; e < 4; ++e) ch[i][j][e] = 0.f;
    #pragma unroll
    for (int kc = 0; kc < 4; ++kc)
        do_mma<4>(smb + BT_B + (uint32_t)kc * 16384u,
                  smb + AT_B + (uint32_t)kc * 16384u, ch, wm, wn, lane);
    epi(ch, smf + 256, smf + 512, smf + 1024, wm, wn, lane);

    __syncthreads();
    if (tid < 128) {
        float a0 = smf[1024 + tid * 2], a1 = smf[1024 + tid * 2 + 1];
        float2 o;
        o.x = 1.f / (1.f + expf(-a0));
        o.y = 1.f / (1.f + expf(-a1));
        ((float2*)out)[b * TT + t0 + tid] = o;
    }
}

// ---------------------------------------------------------------------------
extern "C" void kernel_launch(void* const* d_in, const int* in_sizes, int n_in,
                              void* d_out, int out_size)
{
    const float* x      = (const float*)d_in[0];
    const float* conv_w = (const float*)d_in[1];
    const float* conv_b = (const float*)d_in[2];
    const float* se_w1  = (const float*)d_in[3];
    const float* se_b1  = (const float*)d_in[4];
    const float* se_w2  = (const float*)d_in[5];
    const float* se_b2  = (const float*)d_in[6];
    const float* w1     = (const float*)d_in[7];
    const float* b1     = (const float*)d_in[8];
    const float* w2     = (const float*)d_in[9];
    const float* b2     = (const float*)d_in[10];
    const float* sw     = (const float*)d_in[11];
    const float* sb     = (const float*)d_in[12];
    const float* wo     = (const float*)d_in[13];
    const float* bo     = (const float*)d_in[14];
    float* out = (float*)d_out;

    cudaFuncSetAttribute(main_kernel, cudaFuncAttributeMaxDynamicSharedMemorySize, SMEM_TOT);

    prep_kernel<<<152, 256>>>(w1, w2, sw);
    main_kernel<<<BATCH * 32, 512, SMEM_TOT>>>(x, conv_w, conv_b,
                                               se_w1, se_b1, se_w2, se_b2,
                                               b1, b2, sb, wo, bo, out);
}

// round 17
// speedup vs baseline: 1.0866x; 1.0106x over previous
#include <cuda_runtime.h>
#include <cuda_fp16.h>
#include <math.h>
#include <stdint.h>

#define BATCH 8
#define TT 4096
#define NMELS 26
#define CONV_K 5
#define CH 64
#define WF 32

__device__ uint4 g_w1h[65536];  // 32 chunks x 32KB fp16 swizzled [n256][k64]
__device__ uint4 g_swh[8192];   //  8 chunks x 16KB [n128][k64]
__device__ uint4 g_w2h[4096];   //  4 chunks x 16KB [n128][k64]

__device__ __forceinline__ uint32_t smem_u32(const void* p) {
    uint32_t a;
    asm("{ .reg .u64 t; cvta.to.shared.u64 t, %1; cvt.u32.u64 %0, t; }" : "=r"(a) : "l"(p));
    return a;
}
__device__ __forceinline__ uint32_t sw128(uint32_t o) { return o ^ ((o >> 3) & 0x70); }
__device__ __forceinline__ void ldsm4(uint32_t (&r)[4], uint32_t a) {
    asm volatile("ldmatrix.sync.aligned.m8n8.x4.shared.b16 {%0,%1,%2,%3}, [%4];"
                 : "=r"(r[0]), "=r"(r[1]), "=r"(r[2]), "=r"(r[3]) : "r"(a));
}
__device__ __forceinline__ void mma16816(float (&d)[4], const uint32_t (&a)[4],
                                         uint32_t b0, uint32_t b1) {
    asm volatile("mma.sync.aligned.m16n8k16.row.col.f32.f16.f16.f32 "
                 "{%0,%1,%2,%3}, {%4,%5,%6,%7}, {%8,%9}, {%0,%1,%2,%3};"
                 : "+f"(d[0]), "+f"(d[1]), "+f"(d[2]), "+f"(d[3])
                 : "r"(a[0]), "r"(a[1]), "r"(a[2]), "r"(a[3]), "r"(b0), "r"(b1));
}
__device__ __forceinline__ void cp16(uint32_t dst, const void* src) {
    asm volatile("cp.async.cg.shared.global [%0], [%1], 16;" :: "r"(dst), "l"(src));
}
#define CP_COMMIT() asm volatile("cp.async.commit_group;" ::: "memory")
#define CP_WAIT(n)  asm volatile("cp.async.wait_group %0;" :: "n"(n) : "memory")

// ---------------------------------------------------------------------------
// prep kernel: 152 blocks, coalesced 64k x 64n weight transpose -> fp16 images
// ---------------------------------------------------------------------------
__global__ __launch_bounds__(256, 4) void prep_kernel(
    const float* __restrict__ w1, const float* __restrict__ w2,
    const float* __restrict__ swp)
{
    __shared__ __align__(16) unsigned short sh[4096];
    const int tid = threadIdx.x;
    const int t = blockIdx.x;
    const float* src; unsigned short* dstbase; int N, n0;
    if (t < 128) {
        int f = t >> 2; n0 = (t & 3) * 64;
        src = w1 + (size_t)f * 64 * 256; N = 256;
        dstbase = (unsigned short*)g_w1h + f * 16384;
    } else if (t < 144) {
        int u = t - 128, j = u >> 1; n0 = (u & 1) * 64;
        src = swp + (size_t)j * 64 * 128; N = 128;
        dstbase = (unsigned short*)g_swh + j * 8192;
    } else {
        int u = t - 144, c = u >> 1; n0 = (u & 1) * 64;
        src = w2 + (size_t)c * 64 * 128; N = 128;
        dstbase = (unsigned short*)g_w2h + c * 8192;
    }
    #pragma unroll
    for (int it = 0; it < 16; ++it) {
        int e = it * 256 + tid, kk = e >> 6, nn = e & 63;
        sh[kk * 64 + nn] = __half_as_ushort(__float2half_rn(src[kk * N + n0 + nn]));
    }
    __syncthreads();
    #pragma unroll
    for (int j2 = 0; j2 < 2; ++j2) {
        int G = tid + 256 * j2, n = G >> 3, grp = G & 7, kk0 = grp * 8;
        uint32_t u[4];
        #pragma unroll
        for (int q = 0; q < 4; ++q) {
            uint32_t lo = sh[(kk0 + 2 * q) * 64 + n];
            uint32_t hi = sh[(kk0 + 2 * q + 1) * 64 + n];
            u[q] = lo | (hi << 16);
        }
        uint32_t off = sw128((uint32_t)((n0 + n) * 128 + kk0 * 2));
        *(uint4*)((char*)dstbase + off) = make_uint4(u[0], u[1], u[2], u[3]);
    }
}

// ---------------------------------------------------------------------------
// main kernel: conv + SE + all GEMMs fused. 256 CTAs x 128 tokens, 512 thr.
// smem: misc@0(5120) | XSH@5120 (160x72 halves) | AT@28160 (4x16KB) |
//       BT@93696 (4x32KB). During prologue BT slots 2,3 hold:
//         cvw@+65536 (33280B) | xs_t@+98816 (26x168 f32 = 17472B) |
//         SEw@+116288 (8512B) | cb@+124800 (256B)
// ---------------------------------------------------------------------------
#define XSH_B 5120
#define AT_B  28160
#define BT_B  93696
#define CVW_B (BT_B + 65536)
#define CVX_B (BT_B + 98816)
#define SEW_B (BT_B + 116288)
#define CBS_B (BT_B + 124800)
#define SMEM_TOT 224768

__device__ __forceinline__ void build_A(uint32_t smb, int f, int slot, int tid,
                                        const uint32_t (&gv)[8])
{
    const int m = tid >> 2, kq = (tid & 3) << 4;
    uint32_t xaddr = smb + XSH_B + (uint32_t)(((m + f) * 72 + kq) * 2);
    uint32_t o = (uint32_t)(m * 128 + kq * 2);
    uint32_t abase = smb + AT_B + (uint32_t)slot * 16384u;
    uint32_t dst0 = abase + sw128(o);
    uint32_t dst1 = abase + sw128(o + 16);
    uint32_t xv[8], h[8];
    asm("ld.shared.v4.b32 {%0,%1,%2,%3}, [%4];"
        : "=r"(xv[0]), "=r"(xv[1]), "=r"(xv[2]), "=r"(xv[3]) : "r"(xaddr));
    asm("ld.shared.v4.b32 {%0,%1,%2,%3}, [%4];"
        : "=r"(xv[4]), "=r"(xv[5]), "=r"(xv[6]), "=r"(xv[7]) : "r"(xaddr + 16));
    #pragma unroll
    for (int i = 0; i < 8; ++i)
        asm("mul.rn.f16x2 %0, %1, %2;" : "=r"(h[i]) : "r"(xv[i]), "r"(gv[i]));
    asm volatile("st.shared.v4.b32 [%0], {%1,%2,%3,%4};"
                 :: "r"(dst0), "r"(h[0]), "r"(h[1]), "r"(h[2]), "r"(h[3]));
    asm volatile("st.shared.v4.b32 [%0], {%1,%2,%3,%4};"
                 :: "r"(dst1), "r"(h[4]), "r"(h[5]), "r"(h[6]), "r"(h[7]));
}

template<int NT>
__device__ __forceinline__ void do_mma(uint32_t abase, uint32_t bbase,
                                       float (&c)[2][NT][4], int wm, int wn, int lane)
{
    uint32_t ra = (uint32_t)((wm * 32 + (lane & 15)) * 128 + ((lane >> 4) << 4));
    uint32_t rb = (uint32_t)((wn * (NT * 8) + (lane & 7) + ((lane >> 4) << 3)) * 128
                             + (((lane >> 3) & 1) << 4));
    #pragma unroll
    for (int ks = 0; ks < 4; ++ks) {
        uint32_t a0[4], a1[4];
        ldsm4(a0, abase + sw128(ra + ks * 32));
        ldsm4(a1, abase + sw128(ra + 2048 + ks * 32));
        #pragma unroll
        for (int nt = 0; nt < NT; nt += 2) {
            uint32_t b4[4];
            ldsm4(b4, bbase + sw128(rb + nt * 1024 + ks * 32));
            mma16816(c[0][nt], a0, b4[0], b4[1]);
            mma16816(c[1][nt], a1, b4[0], b4[1]);
            mma16816(c[0][nt + 1], a0, b4[2], b4[3]);
            mma16816(c[1][nt + 1], a1, b4[2], b4[3]);
        }
    }
}

__device__ __forceinline__ void epi(float (&c)[2][4][4], const float* bias,
                                    const float* wop, float* acc2, int wm, int wn, int lane)
{
    float p[2][2][2];
    #pragma unroll
    for (int mt = 0; mt < 2; ++mt)
        #pragma unroll
        for (int h = 0; h < 2; ++h) { p[mt][h][0] = 0.f; p[mt][h][1] = 0.f; }
    #pragma unroll
    for (int mt = 0; mt < 2; ++mt)
    #pragma unroll
    for (int nt = 0; nt < 4; ++nt) {
        int col = wn * 32 + nt * 8 + 2 * (lane & 3);
        float b0 = bias[col], b1v = bias[col + 1];
        float w00 = wop[2 * col], w01 = wop[2 * col + 1];
        float w10 = wop[2 * col + 2], w11 = wop[2 * col + 3];
        float v;
        v = fmaxf(c[mt][nt][0] + b0, 0.f);  p[mt][0][0] += v * w00; p[mt][0][1] += v * w01;
        v = fmaxf(c[mt][nt][1] + b1v, 0.f); p[mt][0][0] += v * w10; p[mt][0][1] += v * w11;
        v = fmaxf(c[mt][nt][2] + b0, 0.f);  p[mt][1][0] += v * w00; p[mt][1][1] += v * w01;
        v = fmaxf(c[mt][nt][3] + b1v, 0.f); p[mt][1][0] += v * w10; p[mt][1][1] += v * w11;
    }
    #pragma unroll
    for (int mt = 0; mt < 2; ++mt)
        #pragma unroll
        for (int h = 0; h < 2; ++h)
            #pragma unroll
            for (int o = 0; o < 2; ++o) {
                p[mt][h][o] += __shfl_xor_sync(0xffffffffu, p[mt][h][o], 1);
                p[mt][h][o] += __shfl_xor_sync(0xffffffffu, p[mt][h][o], 2);
            }
    if ((lane & 3) == 0)
        #pragma unroll
        for (int mt = 0; mt < 2; ++mt)
            #pragma unroll
            for (int h = 0; h < 2; ++h) {
                int row = wm * 32 + mt * 16 + h * 8 + (lane >> 2);
                atomicAdd(&acc2[row * 2 + 0], p[mt][h][0]);
                atomicAdd(&acc2[row * 2 + 1], p[mt][h][1]);
            }
}

__global__ __launch_bounds__(512, 1) void main_kernel(
    const float* __restrict__ x, const float* __restrict__ cw,
    const float* __restrict__ cb,
    const float* __restrict__ sew1, const float* __restrict__ seb1,
    const float* __restrict__ sew2, const float* __restrict__ seb2,
    const float* __restrict__ b1, const float* __restrict__ b2,
    const float* __restrict__ sb, const float* __restrict__ wo,
    const float* __restrict__ bo, float* __restrict__ out)
{
    extern __shared__ char smc[];
    float* smf = (float*)smc;
    const uint32_t smb = smem_u32(smc);
    const int tid = threadIdx.x, lane = tid & 31, wid = tid >> 5;
    const int wm = wid & 3, wn = wid >> 2;
    const int b = blockIdx.x >> 5, t0 = (blockIdx.x & 31) << 7;
    __half* xsh = (__half*)(smc + XSH_B);

    // B pair0 + conv weights via cp.async
    {
        uint32_t dst = smb + BT_B + (uint32_t)tid * 16;
        const char* src = (const char*)g_w1h + (size_t)tid * 16;
        #pragma unroll
        for (int r = 0; r < 8; ++r) cp16(dst + r * 8192, src + (size_t)r * 8192);
        for (int i = tid; i < 2080; i += 512)
            cp16(smb + CVW_B + (uint32_t)i * 16, (const char*)cw + (size_t)i * 16);
        CP_COMMIT();
    }
    // x slab -> TRANSPOSED smem xs_t[26][168]; row rr = token t0-35+rr
    {
        float* xst = (float*)(smc + CVX_B);
        for (int idx = tid; idx < 164 * 26; idx += 512) {
            int rr = idx / 26, mm = idx - rr * 26;
            int t = t0 - 35 + rr;
            float v = 0.f;
            if (t >= 0 && rr < 163) v = x[((size_t)b * TT + t) * 26 + mm];
            xst[mm * 168 + rr] = v;
        }
    }
    if (tid < 256) smf[tid] = b1[tid];
    if (tid < 128) { smf[256 + tid] = b2[tid]; smf[384 + tid] = sb[tid]; }
    smf[512 + tid] = wo[tid];
    if (tid < 256) smf[1024 + tid] = bo[tid & 1];
    // SE weights + conv bias
    float* w1s  = (float*)(smc + SEW_B);
    float* w2s  = w1s + 1024;
    float* b1se = w1s + 2048;
    float* b2se = w1s + 2064;
    float* cbs  = (float*)(smc + CBS_B);
    for (int idx = tid; idx < 1024; idx += 512) { w1s[idx] = sew1[idx]; w2s[idx] = sew2[idx]; }
    if (tid < 16) b1se[tid] = seb1[tid];
    else if (tid >= 32 && tid < 96) b2se[tid - 32] = seb2[tid - 32];
    else if (tid >= 128 && tid < 192) cbs[tid - 128] = cb[tid - 128];

    CP_WAIT(0);
    __syncthreads();   // cvw + xs_t + B pair0 + SE weights ready

    // ---- fused conv (vectorized): rows 0..158 -> XSH fp16 ------------------
    {
        const int c = tid & 63, rg = tid >> 6;
        const float* xst = (const float*)(smc + CVX_B);
        const float* ws = (const float*)(smc + CVW_B);
        const float cbv = cbs[c];
        for (int sg = 0; sg < 5; ++sg) {
            const int r0 = rg * 20 + sg * 4;
            float acc[4] = {cbv, cbv, cbv, cbv};
            #pragma unroll
            for (int m = 0; m < NMELS; ++m) {
                float4 xa = *(const float4*)(xst + m * 168 + r0);
                float4 xb = *(const float4*)(xst + m * 168 + r0 + 4);
                float xr[8] = {xa.x, xa.y, xa.z, xa.w, xb.x, xb.y, xb.z, xb.w};
                #pragma unroll
                for (int k = 0; k < CONV_K; ++k) {
                    float w = ws[(k * NMELS + m) * 64 + c];
                    #pragma unroll
                    for (int i = 0; i < 4; ++i)
                        acc[i] = fmaf(xr[k + i], w, acc[i]);
                }
            }
            #pragma unroll
            for (int i = 0; i < 4; ++i) {
                int r = r0 + i;
                if (r < 159) {
                    float v = (t0 - 31 + r < 0) ? 0.f : fmaxf(acc[i], 0.f);
                    xsh[r * 72 + c] = __float2half_rn(v);
                }
            }
        }
    }
    __syncthreads();

    // ---- fused SE: sliding means -> sA [128][65] fp32 ----
    float* sA   = (float*)(smc + AT_B);
    __half* aH  = (__half*)(smc + AT_B + 33792);
    float* hidS = (float*)(smc + AT_B + 50176);
    {
        const int c = tid & 63, i0 = (tid >> 6) * 16;
        float s = 0.f;
        #pragma unroll
        for (int r = 0; r < WF; ++r) s += __half2float(xsh[(i0 + r) * 72 + c]);
        sA[i0 * 65 + c] = s * 0.03125f;
        #pragma unroll
        for (int k = 1; k < 16; ++k) {
            s += __half2float(xsh[(i0 + k + 31) * 72 + c])
               - __half2float(xsh[(i0 + k - 1) * 72 + c]);
            sA[(i0 + k) * 65 + c] = s * 0.03125f;
        }
    }
    __syncthreads();
    {   // MLP stage 1: thread = (token, 4 hidden)
        const int i = tid >> 2, jg = (tid & 3) << 2;
        float hid[4];
        #pragma unroll
        for (int j = 0; j < 4; ++j) hid[j] = b1se[jg + j];
        for (int c = 0; c < 64; ++c) {
            float sv = sA[i * 65 + c];
            #pragma unroll
            for (int j = 0; j < 4; ++j)
                hid[j] = fmaf(sv, w1s[c * 16 + jg + j], hid[j]);
        }
        #pragma unroll
        for (int j = 0; j < 4; ++j)
            hidS[i * 17 + jg + j] = fmaxf(hid[j], 0.f);
    }
    __syncthreads();
    {   // MLP stage 2: thread = (token, 16 cols)
        const int i = tid >> 2, cg = (tid & 3) << 4;
        float hv[16];
        #pragma unroll
        for (int j = 0; j < 16; ++j) hv[j] = hidS[i * 17 + j];
        #pragma unroll
        for (int c = 0; c < 16; ++c) {
            float v = b2se[cg + c];
            #pragma unroll
            for (int j = 0; j < 16; ++j)
                v = fmaf(hv[j], w2s[j * 64 + cg + c], v);
            aH[i * 64 + cg + c] = __float2half_rn(1.f / (1.f + expf(-v)));
        }
    }
    __syncthreads();
    uint32_t gv[8];
    {
        const int m = tid >> 2, kq = (tid & 3) << 4;
        const uint32_t* ap = (const uint32_t*)(aH + m * 64 + kq);
        #pragma unroll
        for (int q = 0; q < 8; ++q) gv[q] = ap[q];
    }
    __syncthreads();
    build_A(smb, 0, 0, tid, gv);
    build_A(smb, 1, 1, tid, gv);

    // ----- h1 pass: 16 iterations x 2 frames; cp BEFORE mma -----------------
    float c1[2][8][4];
    #pragma unroll
    for (int i = 0; i < 2; ++i)
        #pragma unroll
        for (int j = 0; j < 8; ++j)
            #pragma unroll
            for (int e = 0; e < 4; ++e) c1[i][j][e] = 0.f;

    for (int f = 0; f < 16; ++f) {
        CP_WAIT(0);
        __syncthreads();
        const int s = f & 1;
        if (f < 15) {
            const int sn = (f + 1) & 1;
            uint32_t dst = smb + BT_B + (uint32_t)(2 * sn) * 32768u + (uint32_t)tid * 16;
            const char* src = (const char*)g_w1h + (size_t)(2 * f + 2) * 32768
                              + (size_t)tid * 16;
            #pragma unroll
            for (int r = 0; r < 8; ++r) cp16(dst + r * 8192, src + (size_t)r * 8192);
            CP_COMMIT();
        }
        do_mma<8>(smb + AT_B + (uint32_t)(2 * s) * 16384u,
                  smb + BT_B + (uint32_t)(2 * s) * 32768u, c1, wm, wn, lane);
        do_mma<8>(smb + AT_B + (uint32_t)(2 * s + 1) * 16384u,
                  smb + BT_B + (uint32_t)(2 * s + 1) * 32768u, c1, wm, wn, lane);
        if (f < 15) {
            const int sn = (f + 1) & 1;
            build_A(smb, 2 * f + 2, 2 * sn, tid, gv);
            build_A(smb, 2 * f + 3, 2 * sn + 1, tid, gv);
        }
    }
    __syncthreads();

    {   // short prologue
        uint32_t dst = smb + BT_B + 2u * 32768u + (uint32_t)tid * 16;
        const char* src = (const char*)g_swh + (size_t)tid * 16;
        #pragma unroll
        for (int r = 0; r < 4; ++r) cp16(dst + r * 8192, src + (size_t)r * 8192);
        CP_COMMIT();
        build_A(smb, 24, 0, tid, gv);
        build_A(smb, 25, 1, tid, gv);
    }

    // h1 epilogue: relu(+bias) -> fp16 H1 (BT slots 0,1)
    #pragma unroll
    for (int mt = 0; mt < 2; ++mt)
    #pragma unroll
    for (int nt = 0; nt < 8; ++nt) {
        int colw = nt * 8 + 2 * (lane & 3);
        int colg = wn * 64 + colw;
        float b0v = smf[colg], b1v = smf[colg + 1];
        int r = wm * 32 + mt * 16 + (lane >> 2);
        uint32_t base = smb + BT_B + wn * 16384;
        float v0 = fmaxf(c1[mt][nt][0] + b0v, 0.f), v1 = fmaxf(c1[mt][nt][1] + b1v, 0.f);
        float v2 = fmaxf(c1[mt][nt][2] + b0v, 0.f), v3 = fmaxf(c1[mt][nt][3] + b1v, 0.f);
        uint32_t p0, p1;
        asm("cvt.rn.f16x2.f32 %0,%1,%2;" : "=r"(p0) : "f"(v1), "f"(v0));
        asm("cvt.rn.f16x2.f32 %0,%1,%2;" : "=r"(p1) : "f"(v3), "f"(v2));
        asm volatile("st.shared.b32 [%0], %1;" :: "r"(base + sw128(r * 128 + colw * 2)), "r"(p0));
        asm volatile("st.shared.b32 [%0], %1;" :: "r"(base + sw128((r + 8) * 128 + colw * 2)), "r"(p1));
    }

    // ----- short pass: 4 iterations x 2 frames -------------------------------
    float cs[2][4][4];
    #pragma unroll
    for (int i = 0; i < 2; ++i)
        #pragma unroll
        for (int j = 0; j < 4; ++j)
            #pragma unroll
            for (int e = 0; e < 4; ++e) cs[i][j][e] = 0.f;
    for (int j = 0; j < 4; ++j) {
        CP_WAIT(0);
        __syncthreads();
        const int s = j & 1;
        if (j < 3) {
            const int sn = (j + 1) & 1;
            uint32_t dst = smb + BT_B + (uint32_t)(2 + sn) * 32768u + (uint32_t)tid * 16;
            const char* src = (const char*)g_swh + (size_t)(2 * j + 2) * 16384
                              + (size_t)tid * 16;
            #pragma unroll
            for (int r = 0; r < 4; ++r) cp16(dst + r * 8192, src + (size_t)r * 8192);
            CP_COMMIT();
        } else {
            uint32_t dst = smb + AT_B + (uint32_t)tid * 16;
            const char* src = (const char*)g_w2h + (size_t)tid * 16;
            #pragma unroll
            for (int r = 0; r < 4; ++r) cp16(dst + r * 8192, src + (size_t)r * 8192);
            CP_COMMIT();
        }
        uint32_t bbase = smb + BT_B + (uint32_t)(2 + s) * 32768u;
        do_mma<4>(smb + AT_B + (uint32_t)(2 * s) * 16384u, bbase, cs, wm, wn, lane);
        do_mma<4>(smb + AT_B + (uint32_t)(2 * s + 1) * 16384u, bbase + 16384u,
                  cs, wm, wn, lane);
        if (j < 3) {
            const int sn = (j + 1) & 1;
            build_A(smb, 26 + 2 * j, 2 * sn, tid, gv);
            build_A(smb, 27 + 2 * j, 2 * sn + 1, tid, gv);
        }
    }
    __syncthreads();

    {   // stage W2 chunks 2,3 -> AT slots 2,3
        uint32_t dst = smb + AT_B + 2u * 16384u + (uint32_t)tid * 16;
        const char* src = (const char*)g_w2h + 32768 + (size_t)tid * 16;
        #pragma unroll
        for (int r = 0; r < 4; ++r) cp16(dst + r * 8192, src + (size_t)r * 8192);
        CP_COMMIT();
    }
    epi(cs, smf + 384, smf + 512 + 256, smf + 1024, wm, wn, lane);
    CP_WAIT(0);
    __syncthreads();

    // ----- h2 pass ------------------------------------------------------------
    float ch[2][4][4];
    #pragma unroll
    for (int i = 0; i < 2; ++i)
        #pragma unroll
        for (int j = 0; j < 4; ++j)
            #pragma unroll
            for (int e = 0; e < 4; ++e) ch[i][j][e] = 0.f;
    #pragma unroll
    for (int kc = 0; kc < 4; ++kc)
        do_mma<4>(smb + BT_B + (uint32_t)kc * 16384u,
                  smb + AT_B + (uint32_t)kc * 16384u, ch, wm, wn, lane);
    epi(ch, smf + 256, smf + 512, smf + 1024, wm, wn, lane);

    __syncthreads();
    if (tid < 128) {
        float a0 = smf[1024 + tid * 2], a1 = smf[1024 + tid * 2 + 1];
        float2 o;
        o.x = 1.f / (1.f + expf(-a0));
        o.y = 1.f / (1.f + expf(-a1));
        ((float2*)out)[b * TT + t0 + tid] = o;
    }
}

// ---------------------------------------------------------------------------
extern "C" void kernel_launch(void* const* d_in, const int* in_sizes, int n_in,
                              void* d_out, int out_size)
{
    const float* x      = (const float*)d_in[0];
    const float* conv_w = (const float*)d_in[1];
    const float* conv_b = (const float*)d_in[2];
    const float* se_w1  = (const float*)d_in[3];
    const float* se_b1  = (const float*)d_in[4];
    const float* se_w2  = (const float*)d_in[5];
    const float* se_b2  = (const float*)d_in[6];
    const float* w1     = (const float*)d_in[7];
    const float* b1     = (const float*)d_in[8];
    const float* w2     = (const float*)d_in[9];
    const float* b2     = (const float*)d_in[10];
    const float* sw     = (const float*)d_in[11];
    const float* sb     = (const float*)d_in[12];
    const float* wo     = (const float*)d_in[13];
    const float* bo     = (const float*)d_in[14];
    float* out = (float*)d_out;

    cudaFuncSetAttribute(main_kernel, cudaFuncAttributeMaxDynamicSharedMemorySize, SMEM_TOT);

    prep_kernel<<<152, 256>>>(w1, w2, sw);
    main_kernel<<<BATCH * 32, 512, SMEM_TOT>>>(x, conv_w, conv_b,
                                               se_w1, se_b1, se_w2, se_b2,
                                               b1, b2, sb, wo, bo, out);
}